// round 5
// baseline (speedup 1.0000x reference)
#include <cuda_runtime.h>
#include <math.h>

#define N_ROWS 131072
#define D_DIM  512
#define M_SUB  4
#define K_CODES 256
#define DM_DIM 128

// scratch: xr = x @ rotate  (268 MB) — static device array (no allocations allowed)
__device__ float g_xr[(size_t)N_ROWS * D_DIM];
__device__ double g_acc[4]; // 0:soft_d sum, 1:hard_d sum, 2:joint sum, 3:reg sum

__global__ void zero_acc_kernel() {
    if (threadIdx.x < 4) g_acc[threadIdx.x] = 0.0;
}

// ---------------------------------------------------------------------------
// Kernel 1: xr = x (131072x512) @ rotate (512x512), fp32 tiled SGEMM
// Accumulation: single accumulator per output, strictly ascending k, IEEE FMA
// (bit-matches Eigen/XLA-CPU gebp and typical cublas sgemm accumulation order)
// ---------------------------------------------------------------------------
#define BM 128
#define BN 64
#define BK 16

__global__ __launch_bounds__(256) void sgemm_kernel(const float* __restrict__ A,
                                                    const float* __restrict__ B) {
    __shared__ float As[BK][BM];
    __shared__ float Bs[BK][BN];
    const int tid = threadIdx.x;
    const int tx = tid & 15, ty = tid >> 4;
    const int R0 = blockIdx.y * BM, C0 = blockIdx.x * BN;

    float acc[8][4];
#pragma unroll
    for (int i = 0; i < 8; i++)
#pragma unroll
        for (int j = 0; j < 4; j++) acc[i][j] = 0.f;

    for (int k0 = 0; k0 < D_DIM; k0 += BK) {
        // load A tile (128x16) transposed into As[kk][row]
#pragma unroll
        for (int i = 0; i < 2; i++) {
            int f = tid + i * 256;          // 0..511 float4 slots
            int row = f >> 2, cg = f & 3;   // 4 float4 per row
            float4 v = *(const float4*)(A + (size_t)(R0 + row) * D_DIM + k0 + cg * 4);
            As[cg * 4 + 0][row] = v.x;
            As[cg * 4 + 1][row] = v.y;
            As[cg * 4 + 2][row] = v.z;
            As[cg * 4 + 3][row] = v.w;
        }
        {
            int row = tid >> 4, cg = tid & 15;  // 16 rows x 16 float4
            float4 v = *(const float4*)(B + (size_t)(k0 + row) * D_DIM + C0 + cg * 4);
            *(float4*)(&Bs[row][cg * 4]) = v;
        }
        __syncthreads();

#pragma unroll
        for (int kk = 0; kk < BK; kk++) {
            float a[8], b[4];
#pragma unroll
            for (int i = 0; i < 8; i++) a[i] = As[kk][ty * 8 + i];
#pragma unroll
            for (int j = 0; j < 4; j++) b[j] = Bs[kk][tx * 4 + j];
#pragma unroll
            for (int i = 0; i < 8; i++)
#pragma unroll
                for (int j = 0; j < 4; j++) acc[i][j] = __fmaf_rn(a[i], b[j], acc[i][j]);
        }
        __syncthreads();
    }
#pragma unroll
    for (int i = 0; i < 8; i++) {
        float4 v = make_float4(acc[i][0], acc[i][1], acc[i][2], acc[i][3]);
        *(float4*)(g_xr + (size_t)(R0 + ty * 8 + i) * D_DIM + C0 + tx * 4) = v;
    }
}

// ---------------------------------------------------------------------------
// Kernel 2: reg = sum((R R^T - I)^2)  -> g_acc[3]   (loss-only, tolerance loose)
// ---------------------------------------------------------------------------
__global__ __launch_bounds__(256) void reg_kernel(const float* __restrict__ R) {
    __shared__ float ri[D_DIM];
    __shared__ float part[8];
    const int i = blockIdx.x;
    const int tid = threadIdx.x;
    for (int d = tid; d < D_DIM; d += 256) ri[d] = R[(size_t)i * D_DIM + d];
    __syncthreads();

    const int warp = tid >> 5, lane = tid & 31;
    float accum = 0.f;
    for (int j = warp; j < D_DIM; j += 8) {
        const float* rj = R + (size_t)j * D_DIM;
        float dot = 0.f;
#pragma unroll 4
        for (int k = lane; k < D_DIM; k += 32) dot += ri[k] * rj[k];
#pragma unroll
        for (int off = 16; off; off >>= 1) dot += __shfl_down_sync(0xffffffffu, dot, off);
        if (lane == 0) {
            float v = dot - (j == i ? 1.f : 0.f);
            accum += v * v;
        }
    }
    if (lane == 0) part[warp] = accum;
    __syncthreads();
    if (tid == 0) {
        float s = 0.f;
#pragma unroll
        for (int w = 0; w < 8; w++) s += part[w];
        atomicAdd(&g_acc[3], (double)s);
    }
}

// ---------------------------------------------------------------------------
// Kernel 3: fused distance / softmax / argmax / soft-recon / losses
// grid (M, 512), 256 threads, 256 rows per block processed in 32-row superchunks.
//
// BIT-EXACT replication of the reference's fp32 arithmetic:
//   x2   = sum_d fl(s_d*s_d)    (rounded mul, sequential ascending scalar adds)
//   c2_k = sum_d fl(c_d*c_d)    (same pattern)
//   xc_k = fma-chain over d ascending, single accumulator (Eigen gebp order)
//   dist = fl( fl(x2 - 2*xc) + c2 ),  logits = -dist
//   argmax with lowest-index tie-break (jnp.argmax semantics)
// ---------------------------------------------------------------------------
#define ROWS_PER_BLOCK 256
#define SUPER 32
#define CHUNK 4
#define KPAD 257
#define SPAD 129
#define PQ_SMEM_FLOATS (DM_DIM * KPAD + K_CODES + SUPER * SPAD + SUPER + CHUNK * K_CODES + 4 + 4 + 4 + 32 + 32)
#define PQ_SMEM_BYTES (PQ_SMEM_FLOATS * 4)

__global__ __launch_bounds__(256) void pq_kernel(const float* __restrict__ codebook,
                                                 float* __restrict__ out) {
    extern __shared__ float sm[];
    float* ct     = sm;                        // [128][257] codebook transposed
    float* c2s    = ct + DM_DIM * KPAD;        // [256]
    float* s32    = c2s + K_CODES;             // [32][129] splits superchunk
    float* x2s    = s32 + SUPER * SPAD;        // [32]
    float* probs  = x2s + SUPER;               // [4][256] (16B aligned)
    float* rowmax = probs + CHUNK * K_CODES;   // [4]
    float* invs   = rowmax + 4;                // [4]
    int*   rowarg = (int*)(invs + 4);          // [4]
    float* redv   = (float*)(rowarg + 4);      // [32]
    int*   redi   = (int*)(redv + 32);         // [32]

    const int m   = blockIdx.x;
    const int nb  = blockIdx.y;
    const int tid = threadIdx.x;
    const int lane = tid & 31, warp = tid >> 5;

    // stage codebook[m] transposed: ct[d][k]
    const float* cbm = codebook + (size_t)m * K_CODES * DM_DIM;
    for (int idx4 = tid; idx4 < K_CODES * DM_DIM / 4; idx4 += 256) {
        int k = idx4 >> 5;               // DM/4 = 32 float4 per code row
        int d = (idx4 & 31) << 2;
        float4 v = *(const float4*)(cbm + (size_t)k * DM_DIM + d);
        ct[(d + 0) * KPAD + k] = v.x;
        ct[(d + 1) * KPAD + k] = v.y;
        ct[(d + 2) * KPAD + k] = v.z;
        ct[(d + 3) * KPAD + k] = v.w;
    }
    __syncthreads();
    {   // c2[k] = sum_d fl(c*c), sequential ascending adds (reference order)
        float s = 0.f;
        for (int d = 0; d < DM_DIM; d++) {
            float c = ct[d * KPAD + tid];
            s = __fadd_rn(s, __fmul_rn(c, c));
        }
        c2s[tid] = s;
    }
    __syncthreads();

    float aS = 0.f, aH = 0.f, aJ = 0.f;
    const int base = nb * ROWS_PER_BLOCK;

    for (int scBase = 0; scBase < ROWS_PER_BLOCK; scBase += SUPER) {
        const int rS = base + scBase;
        // load 32 rows' split vectors (1024 float4, 4 per thread)
#pragma unroll
        for (int t = 0; t < 4; t++) {
            int idx = tid + t * 256;
            int row = idx >> 5, d4 = (idx & 31) << 2;
            float4 v = *(const float4*)(g_xr + (size_t)(rS + row) * D_DIM + m * DM_DIM + d4);
            s32[row * SPAD + d4 + 0] = v.x;
            s32[row * SPAD + d4 + 1] = v.y;
            s32[row * SPAD + d4 + 2] = v.z;
            s32[row * SPAD + d4 + 3] = v.w;
        }
        __syncthreads();
        // x2 for 32 rows: one thread per row, strictly sequential d ascending,
        // rounded mul then rounded add (matches materialized splits*splits + sum)
        if (tid < SUPER) {
            const float* srow = s32 + tid * SPAD;
            float acc = 0.f;
            for (int d = 0; d < DM_DIM; d++) {
                float s = srow[d];
                acc = __fadd_rn(acc, __fmul_rn(s, s));
            }
            x2s[tid] = acc;
        }
        __syncthreads();

        for (int sc = 0; sc < SUPER; sc += CHUNK) {
            const int r0 = rS + sc;
            // pass1: logits for all 256 codes x 4 rows (thread = code k)
            float lg[4];
            {
                float a0 = 0.f, a1 = 0.f, a2 = 0.f, a3 = 0.f;
                const float* sp0 = s32 + (sc + 0) * SPAD;
                const float* sp1 = s32 + (sc + 1) * SPAD;
                const float* sp2 = s32 + (sc + 2) * SPAD;
                const float* sp3 = s32 + (sc + 3) * SPAD;
#pragma unroll 4
                for (int d = 0; d < DM_DIM; d++) {
                    float cv = ct[d * KPAD + tid];
                    a0 = __fmaf_rn(cv, sp0[d], a0);
                    a1 = __fmaf_rn(cv, sp1[d], a1);
                    a2 = __fmaf_rn(cv, sp2[d], a2);
                    a3 = __fmaf_rn(cv, sp3[d], a3);
                }
                float c2v = c2s[tid];
                // dist = fl( fl(x2 - 2*xc) + c2 ), logits = -dist
                float t0 = __fadd_rn(x2s[sc + 0], -(2.0f * a0));
                float t1 = __fadd_rn(x2s[sc + 1], -(2.0f * a1));
                float t2 = __fadd_rn(x2s[sc + 2], -(2.0f * a2));
                float t3 = __fadd_rn(x2s[sc + 3], -(2.0f * a3));
                lg[0] = -__fadd_rn(t0, c2v);
                lg[1] = -__fadd_rn(t1, c2v);
                lg[2] = -__fadd_rn(t2, c2v);
                lg[3] = -__fadd_rn(t3, c2v);
            }

            // per-row argmax/max (lowest-index tie-break, matching jnp.argmax)
#pragma unroll
            for (int j = 0; j < 4; j++) {
                float v = lg[j];
                int ix = tid;
#pragma unroll
                for (int off = 16; off; off >>= 1) {
                    float ov = __shfl_down_sync(0xffffffffu, v, off);
                    int   oi = __shfl_down_sync(0xffffffffu, ix, off);
                    if (ov > v || (ov == v && oi < ix)) { v = ov; ix = oi; }
                }
                if (lane == 0) { redv[warp * 4 + j] = v; redi[warp * 4 + j] = ix; }
            }
            __syncthreads();
            if (tid < 4) {
                float v = redv[tid];
                int ix = redi[tid];
#pragma unroll
                for (int w = 1; w < 8; w++) {
                    float ov = redv[w * 4 + tid];
                    int   oi = redi[w * 4 + tid];
                    if (ov > v || (ov == v && oi < ix)) { v = ov; ix = oi; }
                }
                rowmax[tid] = v;
                rowarg[tid] = ix;
                out[(size_t)(r0 + tid) * M_SUB + m] = (float)ix;  // hard code
            }
            __syncthreads();

            // exp + sum (loss path, tolerance loose)
#pragma unroll
            for (int j = 0; j < 4; j++) {
                float e = __expf(lg[j] - rowmax[j]);
                probs[j * K_CODES + tid] = e;
#pragma unroll
                for (int off = 16; off; off >>= 1) e += __shfl_down_sync(0xffffffffu, e, off);
                if (lane == 0) redv[warp * 4 + j] = e;
            }
            __syncthreads();
            if (tid < 4) {
                float s = 0.f;
#pragma unroll
                for (int w = 0; w < 8; w++) s += redv[w * 4 + tid];
                invs[tid] = 1.f / s;
            }
            __syncthreads();

            // pass2: soft reconstruction + losses (thread = (d, row-pair))
            {
                const int d = tid & 127, g = tid >> 7;
                const int jA = 2 * g, jB = 2 * g + 1;
                float sA = 0.f, sB = 0.f;
                const float* ctd = ct + d * KPAD;
                const float4* pA = (const float4*)(probs + jA * K_CODES);
                const float4* pB = (const float4*)(probs + jB * K_CODES);
#pragma unroll 8
                for (int k4 = 0; k4 < K_CODES / 4; k4++) {
                    float4 a = pA[k4], b = pB[k4];
                    float c0 = ctd[4 * k4 + 0];
                    float c1 = ctd[4 * k4 + 1];
                    float c2v = ctd[4 * k4 + 2];
                    float c3 = ctd[4 * k4 + 3];
                    sA += a.x * c0 + a.y * c1 + a.z * c2v + a.w * c3;
                    sB += b.x * c0 + b.y * c1 + b.z * c2v + b.w * c3;
                }
                sA *= invs[jA];
                sB *= invs[jB];
                float spA = s32[(sc + jA) * SPAD + d], spB = s32[(sc + jB) * SPAD + d];
                float hA = ctd[rowarg[jA]], hB = ctd[rowarg[jB]];
                float dsA = spA - sA, dsB = spB - sB;
                float dhA = spA - hA, dhB = spB - hB;
                float djA = sA - hA,  djB = sB - hB;
                aS += dsA * dsA + dsB * dsB;
                aH += dhA * dhA + dhB * dhB;
                aJ += djA * djA + djB * djB;
            }
            __syncthreads();
        }
        __syncthreads();
    }

    // block-reduce the 3 loss partials (reuse probs buffer: 1024 floats)
    float* red3 = probs;
    red3[tid] = aS; red3[256 + tid] = aH; red3[512 + tid] = aJ;
    __syncthreads();
    for (int s = 128; s > 0; s >>= 1) {
        if (tid < s) {
            red3[tid]       += red3[tid + s];
            red3[256 + tid] += red3[256 + tid + s];
            red3[512 + tid] += red3[512 + tid + s];
        }
        __syncthreads();
    }
    if (tid == 0) {
        atomicAdd(&g_acc[0], (double)red3[0]);
        atomicAdd(&g_acc[1], (double)red3[256]);
        atomicAdd(&g_acc[2], (double)red3[512]);
    }
}

// ---------------------------------------------------------------------------
// Kernel 4: combine loss
// ---------------------------------------------------------------------------
__global__ void finalize_kernel(float* out, int out_size) {
    if (threadIdx.x == 0) {
        double inv = 1.0 / ((double)N_ROWS * (double)DM_DIM);
        double loss = 0.1 * g_acc[0] * inv + g_acc[1] * inv + 0.1 * g_acc[2] * inv
                    + 0.01 * (g_acc[3] / ((double)D_DIM * (double)D_DIM));
        out[out_size - 1] = (float)loss;
    }
}

extern "C" void kernel_launch(void* const* d_in, const int* in_sizes, int n_in,
                              void* d_out, int out_size) {
    const float* x        = (const float*)d_in[0];
    const float* codebook = (const float*)d_in[1];
    const float* rotate   = (const float*)d_in[2];
    float* out = (float*)d_out;

    cudaFuncSetAttribute(pq_kernel, cudaFuncAttributeMaxDynamicSharedMemorySize, PQ_SMEM_BYTES);

    zero_acc_kernel<<<1, 32>>>();
    sgemm_kernel<<<dim3(D_DIM / BN, N_ROWS / BM), 256>>>(x, rotate);
    reg_kernel<<<D_DIM, 256>>>(rotate);
    pq_kernel<<<dim3(M_SUB, N_ROWS / ROWS_PER_BLOCK), 256, PQ_SMEM_BYTES>>>(codebook, out);
    finalize_kernel<<<1, 32>>>(out, out_size);
}

// round 7
// speedup vs baseline: 2.1779x; 2.1779x over previous
#include <cuda_runtime.h>
#include <math.h>

#define N_ROWS 131072
#define D_DIM  512
#define M_SUB  4
#define K_CODES 256
#define DM_DIM 128

// scratch: xr = x @ rotate  (268 MB) — static device array (no allocations allowed)
__device__ float g_xr[(size_t)N_ROWS * D_DIM];
__device__ double g_acc[4]; // 0:soft_d sum, 1:hard_d sum, 2:joint sum, 3:reg sum

__global__ void zero_acc_kernel() {
    if (threadIdx.x < 4) g_acc[threadIdx.x] = 0.0;
}

// ---------------------------------------------------------------------------
// Kernel 1: xr = x (131072x512) @ rotate (512x512), fp32 tiled SGEMM
// 128x128 tile, BK=16, 256 threads, 8x8 per thread, float4 shared loads.
// BIT-EXACT CONTRACT: each output = single accumulator, strictly ascending k,
// IEEE FMA. (Matches reference; verified rel_err==0 in round 5.)
// ---------------------------------------------------------------------------
#define GBM 128
#define GBN 128
#define GBK 16

__global__ __launch_bounds__(256) void sgemm_kernel(const float* __restrict__ A,
                                                    const float* __restrict__ B) {
    __shared__ float As[GBK][GBM];   // transposed A tile
    __shared__ float Bs[GBK][GBN];
    const int tid = threadIdx.x;
    const int tx = tid & 15, ty = tid >> 4;
    const int R0 = blockIdx.y * GBM, C0 = blockIdx.x * GBN;

    float acc[8][8];
#pragma unroll
    for (int i = 0; i < 8; i++)
#pragma unroll
        for (int j = 0; j < 8; j++) acc[i][j] = 0.f;

    for (int k0 = 0; k0 < D_DIM; k0 += GBK) {
        // A tile: 128 rows x 16 k = 512 float4, 2 per thread, store transposed
#pragma unroll
        for (int t = 0; t < 2; t++) {
            int f = tid + t * 256;
            int row = f >> 2, c4 = f & 3;
            float4 v = *(const float4*)(A + (size_t)(R0 + row) * D_DIM + k0 + c4 * 4);
            As[c4 * 4 + 0][row] = v.x;
            As[c4 * 4 + 1][row] = v.y;
            As[c4 * 4 + 2][row] = v.z;
            As[c4 * 4 + 3][row] = v.w;
        }
        // B tile: 16 rows x 128 = 512 float4, 2 per thread
#pragma unroll
        for (int t = 0; t < 2; t++) {
            int f = tid + t * 256;
            int row = f >> 5, c4 = f & 31;
            float4 v = *(const float4*)(B + (size_t)(k0 + row) * D_DIM + C0 + c4 * 4);
            *(float4*)(&Bs[row][c4 * 4]) = v;
        }
        __syncthreads();

#pragma unroll
        for (int kk = 0; kk < GBK; kk++) {
            float a[8], b[8];
            *(float4*)(a)     = *(const float4*)(&As[kk][ty * 8]);
            *(float4*)(a + 4) = *(const float4*)(&As[kk][ty * 8 + 4]);
            *(float4*)(b)     = *(const float4*)(&Bs[kk][tx * 8]);
            *(float4*)(b + 4) = *(const float4*)(&Bs[kk][tx * 8 + 4]);
#pragma unroll
            for (int i = 0; i < 8; i++)
#pragma unroll
                for (int j = 0; j < 8; j++) acc[i][j] = __fmaf_rn(a[i], b[j], acc[i][j]);
        }
        __syncthreads();
    }
#pragma unroll
    for (int i = 0; i < 8; i++) {
        float* orow = g_xr + (size_t)(R0 + ty * 8 + i) * D_DIM + C0 + tx * 8;
        *(float4*)(orow)     = make_float4(acc[i][0], acc[i][1], acc[i][2], acc[i][3]);
        *(float4*)(orow + 4) = make_float4(acc[i][4], acc[i][5], acc[i][6], acc[i][7]);
    }
}

// ---------------------------------------------------------------------------
// Kernel 2: reg = sum((R R^T - I)^2)  -> g_acc[3]   (loss-only, tolerance loose)
// ---------------------------------------------------------------------------
__global__ __launch_bounds__(256) void reg_kernel(const float* __restrict__ R) {
    __shared__ float ri[D_DIM];
    __shared__ float part[8];
    const int i = blockIdx.x;
    const int tid = threadIdx.x;
    for (int d = tid; d < D_DIM; d += 256) ri[d] = R[(size_t)i * D_DIM + d];
    __syncthreads();

    const int warp = tid >> 5, lane = tid & 31;
    float accum = 0.f;
    for (int j = warp; j < D_DIM; j += 8) {
        const float* rj = R + (size_t)j * D_DIM;
        float dot = 0.f;
#pragma unroll 4
        for (int k = lane; k < D_DIM; k += 32) dot += ri[k] * rj[k];
#pragma unroll
        for (int off = 16; off; off >>= 1) dot += __shfl_down_sync(0xffffffffu, dot, off);
        if (lane == 0) {
            float v = dot - (j == i ? 1.f : 0.f);
            accum += v * v;
        }
    }
    if (lane == 0) part[warp] = accum;
    __syncthreads();
    if (tid == 0) {
        float s = 0.f;
#pragma unroll
        for (int w = 0; w < 8; w++) s += part[w];
        atomicAdd(&g_acc[3], (double)s);
    }
}

// ---------------------------------------------------------------------------
// Kernel 3: fused distance / softmax / argmax / soft-recon / losses
// 512 threads, grid (M, 512), 256 rows per block in 32-row superchunks.
//
// BIT-EXACT logits path (identical arithmetic to the round-5 passing kernel):
//   x2   = sum_d fl(s_d*s_d)       sequential ascending scalar adds
//   c2_k = sum_d fl(c_d*c_d)       sequential ascending scalar adds
//   xc_k = single-accumulator FMA chain, ascending d
//   dist = fl( fl(x2 - 2*xc) + c2 ),  logits = -dist
//   argmax lowest-index tie-break (jnp.argmax semantics)
//
// pass1: register tiling 4 rows x 4 codes/thread, float4 LDS -> FMA-bound.
// pass2 (loss-only): 4 rows x 2 dims/thread, float4 probs loads.
// codebook k-major with 132-float row pad (33 odd 16B units: conflict-free
// float4 column access).
// ---------------------------------------------------------------------------
#define ROWS_PB 256
#define SUPER 32
#define CPAD 132
#define LPAD 264
#define PQ_SMEM_FLOATS (K_CODES * CPAD + K_CODES + SUPER * CPAD + SUPER + SUPER * LPAD + SUPER + SUPER + SUPER)
#define PQ_SMEM_BYTES (PQ_SMEM_FLOATS * 4)

__global__ __launch_bounds__(512) void pq_kernel(const float* __restrict__ codebook,
                                                 float* __restrict__ out) {
    extern __shared__ float sm[];
    float* cbk    = sm;                        // [256][132] codebook k-major
    float* c2s    = cbk + K_CODES * CPAD;      // [256]
    float* s32    = c2s + K_CODES;             // [32][132] splits superchunk
    float* x2s    = s32 + SUPER * CPAD;        // [32]
    float* lgs    = x2s + SUPER;               // [32][264] logits -> probs (in place)
    float* rowmax = lgs + SUPER * LPAD;        // [32]
    float* rowinv = rowmax + SUPER;            // [32]
    int*   rowarg = (int*)(rowinv + SUPER);    // [32]

    const int m   = blockIdx.x;
    const int nb  = blockIdx.y;
    const int tid = threadIdx.x;
    const int lane = tid & 31, warp = tid >> 5;

    // stage codebook[m] k-major: cbk[k][d], row pad 132
    const float* cbm = codebook + (size_t)m * K_CODES * DM_DIM;
    for (int idx = tid; idx < K_CODES * (DM_DIM / 4); idx += 512) {
        int k = idx >> 5, d4 = idx & 31;
        float4 v = *(const float4*)(cbm + (size_t)k * DM_DIM + d4 * 4);
        *(float4*)(cbk + k * CPAD + d4 * 4) = v;
    }
    __syncthreads();
    if (tid < K_CODES) {   // c2[k]: sequential ascending, rounded mul then add
        const float* ck = cbk + tid * CPAD;
        float s = 0.f;
        for (int d = 0; d < DM_DIM; d++) {
            float c = ck[d];
            s = __fadd_rn(s, __fmul_rn(c, c));
        }
        c2s[tid] = s;
    }
    __syncthreads();

    float aS = 0.f, aH = 0.f, aJ = 0.f;
    const int base = nb * ROWS_PB;

    for (int sc0 = 0; sc0 < ROWS_PB; sc0 += SUPER) {
        const int rS = base + sc0;
        // load 32 rows' split vectors (1024 float4, 2 per thread)
#pragma unroll
        for (int t = 0; t < 2; t++) {
            int idx = tid + t * 512;
            int row = idx >> 5, d4 = idx & 31;
            float4 v = *(const float4*)(g_xr + (size_t)(rS + row) * D_DIM + m * DM_DIM + d4 * 4);
            *(float4*)(s32 + row * CPAD + d4 * 4) = v;
        }
        __syncthreads();
        // x2: one thread per row, strictly sequential ascending d
        if (tid < SUPER) {
            const float* srow = s32 + tid * CPAD;
            float acc = 0.f;
            for (int d = 0; d < DM_DIM; d++) {
                float s = srow[d];
                acc = __fadd_rn(acc, __fmul_rn(s, s));
            }
            x2s[tid] = acc;
        }
        __syncthreads();

        // ---- pass1: logits (32 rows x 256 codes), thread = 4 rows x 4 codes ----
        {
            const int kg = tid & 63;       // codes kg, kg+64, kg+128, kg+192
            const int rg = tid >> 6;       // rows rg*4 .. rg*4+3
            float acc[4][4];
#pragma unroll
            for (int i = 0; i < 4; i++)
#pragma unroll
                for (int j = 0; j < 4; j++) acc[i][j] = 0.f;

            const float* s0 = s32 + (rg * 4 + 0) * CPAD;
            const float* s1 = s32 + (rg * 4 + 1) * CPAD;
            const float* s2 = s32 + (rg * 4 + 2) * CPAD;
            const float* s3 = s32 + (rg * 4 + 3) * CPAD;
            const float* cb0 = cbk + (kg +   0) * CPAD;
            const float* cb1 = cbk + (kg +  64) * CPAD;
            const float* cb2 = cbk + (kg + 128) * CPAD;
            const float* cb3 = cbk + (kg + 192) * CPAD;

#pragma unroll 4
            for (int d = 0; d < DM_DIM; d += 4) {
                float4 sv[4], cv[4];
                sv[0] = *(const float4*)(s0 + d);
                sv[1] = *(const float4*)(s1 + d);
                sv[2] = *(const float4*)(s2 + d);
                sv[3] = *(const float4*)(s3 + d);
                cv[0] = *(const float4*)(cb0 + d);
                cv[1] = *(const float4*)(cb1 + d);
                cv[2] = *(const float4*)(cb2 + d);
                cv[3] = *(const float4*)(cb3 + d);
#pragma unroll
                for (int i = 0; i < 4; i++)
#pragma unroll
                    for (int j = 0; j < 4; j++) {
                        // ascending d within the chain: x,y,z,w
                        acc[i][j] = __fmaf_rn(sv[i].x, cv[j].x, acc[i][j]);
                        acc[i][j] = __fmaf_rn(sv[i].y, cv[j].y, acc[i][j]);
                        acc[i][j] = __fmaf_rn(sv[i].z, cv[j].z, acc[i][j]);
                        acc[i][j] = __fmaf_rn(sv[i].w, cv[j].w, acc[i][j]);
                    }
            }
            // combine: dist = fl( fl(x2 - 2*xc) + c2 ), logit = -dist
#pragma unroll
            for (int i = 0; i < 4; i++) {
                int r = rg * 4 + i;
                float x2v = x2s[r];
#pragma unroll
                for (int j = 0; j < 4; j++) {
                    int k = kg + 64 * j;
                    float t = __fadd_rn(x2v, -(2.0f * acc[i][j]));
                    lgs[r * LPAD + k] = -__fadd_rn(t, c2s[k]);
                }
            }
        }
        __syncthreads();

        // ---- argmax/max per row: 16 warps, 2 rows each ----
        {
#pragma unroll
            for (int rr = warp * 2; rr < warp * 2 + 2; rr++) {
                const float* Lr = lgs + rr * LPAD + lane * 8;
                float4 v0 = *(const float4*)(Lr);
                float4 v1 = *(const float4*)(Lr + 4);
                float bv = v0.x; int bi = lane * 8;
                if (v0.y > bv) { bv = v0.y; bi = lane * 8 + 1; }
                if (v0.z > bv) { bv = v0.z; bi = lane * 8 + 2; }
                if (v0.w > bv) { bv = v0.w; bi = lane * 8 + 3; }
                if (v1.x > bv) { bv = v1.x; bi = lane * 8 + 4; }
                if (v1.y > bv) { bv = v1.y; bi = lane * 8 + 5; }
                if (v1.z > bv) { bv = v1.z; bi = lane * 8 + 6; }
                if (v1.w > bv) { bv = v1.w; bi = lane * 8 + 7; }
#pragma unroll
                for (int off = 16; off; off >>= 1) {
                    float ov = __shfl_down_sync(0xffffffffu, bv, off);
                    int   oi = __shfl_down_sync(0xffffffffu, bi, off);
                    if (ov > bv || (ov == bv && oi < bi)) { bv = ov; bi = oi; }
                }
                if (lane == 0) {
                    rowmax[rr] = bv;
                    rowarg[rr] = bi;
                    out[(size_t)(rS + rr) * M_SUB + m] = (float)bi;  // hard code
                }
            }
        }
        __syncthreads();

        // ---- exp + sum (loss path): thread -> (row = tid>>4, 16 codes) ----
        {
            int r = tid >> 4, sg = tid & 15;
            float* Pr = lgs + r * LPAD + sg * 16;
            float mx = rowmax[r];
            float s = 0.f;
#pragma unroll
            for (int t = 0; t < 4; t++) {
                float4 v = *(float4*)(Pr + t * 4);
                v.x = __expf(v.x - mx);
                v.y = __expf(v.y - mx);
                v.z = __expf(v.z - mx);
                v.w = __expf(v.w - mx);
                s += v.x + v.y + v.z + v.w;
                *(float4*)(Pr + t * 4) = v;
            }
#pragma unroll
            for (int off = 8; off; off >>= 1) s += __shfl_down_sync(0xffffffffu, s, off, 16);
            if (sg == 0) rowinv[r] = 1.f / s;
        }
        __syncthreads();

        // ---- pass2: soft recon + losses, thread = 4 rows x 2 dims ----
        {
            const int dg = tid & 63;       // dims 2*dg, 2*dg+1
            const int rg = tid >> 6;       // rows rg*4 .. rg*4+3
            const int d0 = dg * 2;
            float sf[4][2];
#pragma unroll
            for (int i = 0; i < 4; i++) { sf[i][0] = 0.f; sf[i][1] = 0.f; }

            const float* P0 = lgs + (rg * 4 + 0) * LPAD;
            const float* P1 = lgs + (rg * 4 + 1) * LPAD;
            const float* P2 = lgs + (rg * 4 + 2) * LPAD;
            const float* P3 = lgs + (rg * 4 + 3) * LPAD;

#pragma unroll 4
            for (int k = 0; k < K_CODES; k += 4) {
                float4 p0 = *(const float4*)(P0 + k);
                float4 p1 = *(const float4*)(P1 + k);
                float4 p2 = *(const float4*)(P2 + k);
                float4 p3 = *(const float4*)(P3 + k);
                float2 c0 = *(const float2*)(cbk + (k + 0) * CPAD + d0);
                float2 c1 = *(const float2*)(cbk + (k + 1) * CPAD + d0);
                float2 c2v = *(const float2*)(cbk + (k + 2) * CPAD + d0);
                float2 c3 = *(const float2*)(cbk + (k + 3) * CPAD + d0);
                sf[0][0] += p0.x * c0.x + p0.y * c1.x + p0.z * c2v.x + p0.w * c3.x;
                sf[0][1] += p0.x * c0.y + p0.y * c1.y + p0.z * c2v.y + p0.w * c3.y;
                sf[1][0] += p1.x * c0.x + p1.y * c1.x + p1.z * c2v.x + p1.w * c3.x;
                sf[1][1] += p1.x * c0.y + p1.y * c1.y + p1.z * c2v.y + p1.w * c3.y;
                sf[2][0] += p2.x * c0.x + p2.y * c1.x + p2.z * c2v.x + p2.w * c3.x;
                sf[2][1] += p2.x * c0.y + p2.y * c1.y + p2.z * c2v.y + p2.w * c3.y;
                sf[3][0] += p3.x * c0.x + p3.y * c1.x + p3.z * c2v.x + p3.w * c3.x;
                sf[3][1] += p3.x * c0.y + p3.y * c1.y + p3.z * c2v.y + p3.w * c3.y;
            }
#pragma unroll
            for (int i = 0; i < 4; i++) {
                int r = rg * 4 + i;
                float inv = rowinv[r];
                int ka = rowarg[r];
#pragma unroll
                for (int dd = 0; dd < 2; dd++) {
                    int d = d0 + dd;
                    float soft = sf[i][dd] * inv;
                    float sp = s32[r * CPAD + d];
                    float hd = cbk[ka * CPAD + d];
                    float ds = sp - soft, dh = sp - hd, dj = soft - hd;
                    aS += ds * ds;
                    aH += dh * dh;
                    aJ += dj * dj;
                }
            }
        }
        __syncthreads();
    }

    // block-reduce the 3 loss partials (reuse lgs as scratch: needs 1536 floats)
    lgs[tid] = aS; lgs[512 + tid] = aH; lgs[1024 + tid] = aJ;
    __syncthreads();
    for (int s = 256; s > 0; s >>= 1) {
        if (tid < s) {
            lgs[tid]        += lgs[tid + s];
            lgs[512 + tid]  += lgs[512 + tid + s];
            lgs[1024 + tid] += lgs[1024 + tid + s];
        }
        __syncthreads();
    }
    if (tid == 0) {
        atomicAdd(&g_acc[0], (double)lgs[0]);
        atomicAdd(&g_acc[1], (double)lgs[512]);
        atomicAdd(&g_acc[2], (double)lgs[1024]);
    }
}

// ---------------------------------------------------------------------------
// Kernel 4: combine loss
// ---------------------------------------------------------------------------
__global__ void finalize_kernel(float* out, int out_size) {
    if (threadIdx.x == 0) {
        double inv = 1.0 / ((double)N_ROWS * (double)DM_DIM);
        double loss = 0.1 * g_acc[0] * inv + g_acc[1] * inv + 0.1 * g_acc[2] * inv
                    + 0.01 * (g_acc[3] / ((double)D_DIM * (double)D_DIM));
        out[out_size - 1] = (float)loss;
    }
}

extern "C" void kernel_launch(void* const* d_in, const int* in_sizes, int n_in,
                              void* d_out, int out_size) {
    const float* x        = (const float*)d_in[0];
    const float* codebook = (const float*)d_in[1];
    const float* rotate   = (const float*)d_in[2];
    float* out = (float*)d_out;

    cudaFuncSetAttribute(pq_kernel, cudaFuncAttributeMaxDynamicSharedMemorySize, PQ_SMEM_BYTES);

    zero_acc_kernel<<<1, 32>>>();
    sgemm_kernel<<<dim3(D_DIM / GBN, N_ROWS / GBM), 256>>>(x, rotate);
    reg_kernel<<<D_DIM, 256>>>(rotate);
    pq_kernel<<<dim3(M_SUB, N_ROWS / ROWS_PB), 512, PQ_SMEM_BYTES>>>(codebook, out);
    finalize_kernel<<<1, 32>>>(out, out_size);
}

// round 8
// speedup vs baseline: 2.3205x; 1.0655x over previous
#include <cuda_runtime.h>
#include <math.h>

#define N_ROWS 131072
#define D_DIM  512
#define M_SUB  4
#define K_CODES 256
#define DM_DIM 128

typedef unsigned long long u64;

// ---- packed fp32x2 helpers (two independent IEEE-754 rn FMAs per instr) ----
__device__ __forceinline__ u64 pack_dup(float a) {
    u64 r; asm("mov.b64 %0, {%1, %1};" : "=l"(r) : "f"(a)); return r;
}
__device__ __forceinline__ void fma2(u64& d, u64 a, u64 b) {
    asm("fma.rn.f32x2 %0, %1, %2, %0;" : "+l"(d) : "l"(a), "l"(b));
}
__device__ __forceinline__ float2 unpk(u64 v) {
    float lo, hi; asm("mov.b64 {%0, %1}, %2;" : "=f"(lo), "=f"(hi) : "l"(v));
    return make_float2(lo, hi);
}

// scratch: xr = x @ rotate  (268 MB) — static device array (no allocations allowed)
__device__ float g_xr[(size_t)N_ROWS * D_DIM];
__device__ double g_acc[4]; // 0:soft_d sum, 1:hard_d sum, 2:joint sum, 3:reg sum

__global__ void zero_acc_kernel() {
    if (threadIdx.x < 4) g_acc[threadIdx.x] = 0.0;
}

// ---------------------------------------------------------------------------
// Kernel 1: xr = x (131072x512) @ rotate (512x512), fp32 tiled SGEMM
// 128x128 tile, BK=16, 256 threads, 8 rows x 4 col-pairs per thread, FFMA2.
// BIT-EXACT CONTRACT: each output = single accumulator, strictly ascending k,
// IEEE rn FMA (f32x2 lanes are independent IEEE fp32 FMAs).
// ---------------------------------------------------------------------------
#define GBM 128
#define GBN 128
#define GBK 16

__global__ __launch_bounds__(256) void sgemm_kernel(const float* __restrict__ A,
                                                    const float* __restrict__ B) {
    __shared__ float As[GBK][GBM];   // transposed A tile
    __shared__ float Bs[GBK][GBN];
    const int tid = threadIdx.x;
    const int tx = tid & 15, ty = tid >> 4;
    const int R0 = blockIdx.y * GBM, C0 = blockIdx.x * GBN;

    u64 acc2[8][4];
#pragma unroll
    for (int i = 0; i < 8; i++)
#pragma unroll
        for (int j = 0; j < 4; j++) acc2[i][j] = 0ull;

    for (int k0 = 0; k0 < D_DIM; k0 += GBK) {
        // A tile: 128 rows x 16 k = 512 float4, 2 per thread, store transposed
#pragma unroll
        for (int t = 0; t < 2; t++) {
            int f = tid + t * 256;
            int row = f >> 2, c4 = f & 3;
            float4 v = *(const float4*)(A + (size_t)(R0 + row) * D_DIM + k0 + c4 * 4);
            As[c4 * 4 + 0][row] = v.x;
            As[c4 * 4 + 1][row] = v.y;
            As[c4 * 4 + 2][row] = v.z;
            As[c4 * 4 + 3][row] = v.w;
        }
        // B tile: 16 rows x 128 = 512 float4, 2 per thread
#pragma unroll
        for (int t = 0; t < 2; t++) {
            int f = tid + t * 256;
            int row = f >> 5, c4 = f & 31;
            float4 v = *(const float4*)(B + (size_t)(k0 + row) * D_DIM + C0 + c4 * 4);
            *(float4*)(&Bs[row][c4 * 4]) = v;
        }
        __syncthreads();

#pragma unroll
        for (int kk = 0; kk < GBK; kk++) {
            float a[8];
            *(float4*)(a)     = *(const float4*)(&As[kk][ty * 8]);
            *(float4*)(a + 4) = *(const float4*)(&As[kk][ty * 8 + 4]);
            ulonglong2 b01 = *(const ulonglong2*)(&Bs[kk][tx * 8]);
            ulonglong2 b23 = *(const ulonglong2*)(&Bs[kk][tx * 8 + 4]);
            u64 bb0 = b01.x, bb1 = b01.y, bb2 = b23.x, bb3 = b23.y;
#pragma unroll
            for (int i = 0; i < 8; i++) {
                u64 ad = pack_dup(a[i]);
                fma2(acc2[i][0], ad, bb0);
                fma2(acc2[i][1], ad, bb1);
                fma2(acc2[i][2], ad, bb2);
                fma2(acc2[i][3], ad, bb3);
            }
        }
        __syncthreads();
    }
#pragma unroll
    for (int i = 0; i < 8; i++) {
        float* orow = g_xr + (size_t)(R0 + ty * 8 + i) * D_DIM + C0 + tx * 8;
        ulonglong2 v0, v1;
        v0.x = acc2[i][0]; v0.y = acc2[i][1];
        v1.x = acc2[i][2]; v1.y = acc2[i][3];
        *(ulonglong2*)(orow)     = v0;
        *(ulonglong2*)(orow + 4) = v1;
    }
}

// ---------------------------------------------------------------------------
// Kernel 2: reg = sum((R R^T - I)^2)  -> g_acc[3]   (loss-only, tolerance loose)
// ---------------------------------------------------------------------------
__global__ __launch_bounds__(256) void reg_kernel(const float* __restrict__ R) {
    __shared__ float ri[D_DIM];
    __shared__ float part[8];
    const int i = blockIdx.x;
    const int tid = threadIdx.x;
    for (int d = tid; d < D_DIM; d += 256) ri[d] = R[(size_t)i * D_DIM + d];
    __syncthreads();

    const int warp = tid >> 5, lane = tid & 31;
    float accum = 0.f;
    for (int j = warp; j < D_DIM; j += 8) {
        const float* rj = R + (size_t)j * D_DIM;
        float dot = 0.f;
#pragma unroll 4
        for (int k = lane; k < D_DIM; k += 32) dot += ri[k] * rj[k];
#pragma unroll
        for (int off = 16; off; off >>= 1) dot += __shfl_down_sync(0xffffffffu, dot, off);
        if (lane == 0) {
            float v = dot - (j == i ? 1.f : 0.f);
            accum += v * v;
        }
    }
    if (lane == 0) part[warp] = accum;
    __syncthreads();
    if (tid == 0) {
        float s = 0.f;
#pragma unroll
        for (int w = 0; w < 8; w++) s += part[w];
        atomicAdd(&g_acc[3], (double)s);
    }
}

// ---------------------------------------------------------------------------
// Kernel 3: fused distance / softmax / argmax / soft-recon / losses
// 256 threads, grid (M, 512), 256 rows per block in 32-row superchunks.
//
// BIT-EXACT logits path (identical arithmetic to round-5/7 passing kernels):
//   x2   = sum_d fl(s*s) sequential ascending;  c2 same
//   xc   = single-accumulator IEEE-rn FMA chain, ascending d (f32x2 lanes
//          are independent -> per-(row,code) chain unchanged)
//   dist = fl( fl(x2 - 2*xc) + c2 ),  logits = -dist
//   argmax lowest-index tie-break
//
// pass1: FFMA2, rows packed in pairs (splits staged d-major s32t[d][32]),
//        thread = 4 row-pairs x 4 codes.
// pass2: FFMA2, probs stored code-major pair-packed probsT[k][32],
//        thread = 2 row-pairs x 4 dims x all codes.
// ---------------------------------------------------------------------------
#define ROWS_PB 256
#define SUPER 32
#define CPAD 132
#define PP 34
#define RP 32
#define PQ_SMEM_FLOATS (K_CODES * CPAD + 256 + 256 + 128 * RP + K_CODES * PP + 64 + 64 + 32 + 32 + 64 + 32)
#define PQ_SMEM_BYTES (PQ_SMEM_FLOATS * 4)

__global__ __launch_bounds__(256) void pq_kernel(const float* __restrict__ codebook,
                                                 float* __restrict__ out) {
    extern __shared__ float sm[];
    float* cbk    = sm;                         // [256][132] codebook k-major
    float* c2s    = cbk + K_CODES * CPAD;       // [256]
    float* x2all  = c2s + 256;                  // [256] x2 for all block rows
    float* s32t   = x2all + 256;                // [128][32] splits d-major
    float* probsT = s32t + 128 * RP;            // [256][34] probs code-major
    float* wv     = probsT + K_CODES * PP;      // [8 warps][8 rows] max partials
    float* wsum   = wv + 64;                    // [8][8] sum partials
    float* rowmax = wsum + 64;                  // [32]
    float* rowinv = rowmax + 32;                // [32]
    int*   wi     = (int*)(rowinv + 32);        // [64]
    int*   rowarg = wi + 64;                    // [32]

    const int m   = blockIdx.x;
    const int nb  = blockIdx.y;
    const int tid = threadIdx.x;
    const int lane = tid & 31, warp = tid >> 5;
    const int base = nb * ROWS_PB;

    // stage codebook[m] k-major
    const float* cbm = codebook + (size_t)m * K_CODES * DM_DIM;
    for (int idx = tid; idx < K_CODES * (DM_DIM / 4); idx += 256) {
        int k = idx >> 5, d4 = idx & 31;
        *(float4*)(cbk + k * CPAD + d4 * 4) = *(const float4*)(cbm + (size_t)k * DM_DIM + d4 * 4);
    }
    __syncthreads();
    {   // c2[k]: sequential ascending, rounded mul then add
        const float* ck = cbk + tid * CPAD;
        float s = 0.f;
        for (int d = 0; d < DM_DIM; d++) {
            float c = ck[d];
            s = __fadd_rn(s, __fmul_rn(c, c));
        }
        c2s[tid] = s;
    }
    {   // x2 for all 256 rows: one thread per row, strictly sequential ascending d
        const float* xp = g_xr + (size_t)(base + tid) * D_DIM + m * DM_DIM;
        float s = 0.f;
        for (int d = 0; d < DM_DIM; d++) {
            float v = xp[d];
            s = __fadd_rn(s, __fmul_rn(v, v));
        }
        x2all[tid] = s;
    }
    __syncthreads();

    float aS = 0.f, aH = 0.f, aJ = 0.f;

    const int kg = tid & 63, rg = tid >> 6;     // pass1 mapping
    const int dg = tid & 31, rg2 = tid >> 5;    // pass2 mapping
    const int r0 = rg2 * 4, d0 = dg * 4;

    for (int sc0 = 0; sc0 < ROWS_PB; sc0 += SUPER) {
        const int rS = base + sc0;

        // ---- stage splits d-major: s32t[d][row] ----
        {
            int row = tid & 31, dq = tid >> 5;
            const float* xp = g_xr + (size_t)(rS + row) * D_DIM + m * DM_DIM + dq * 16;
#pragma unroll
            for (int t = 0; t < 4; t++) {
                float4 v = *(const float4*)(xp + t * 4);
                int d = dq * 16 + t * 4;
                s32t[(d + 0) * RP + row] = v.x;
                s32t[(d + 1) * RP + row] = v.y;
                s32t[(d + 2) * RP + row] = v.z;
                s32t[(d + 3) * RP + row] = v.w;
            }
        }
        __syncthreads();

        // ---- pass1: xc for 8 rows (4 pairs) x 4 codes per thread, FFMA2 ----
        float lg[8][4];
        {
            u64 acc2[4][4];
#pragma unroll
            for (int p = 0; p < 4; p++)
#pragma unroll
                for (int j = 0; j < 4; j++) acc2[p][j] = 0ull;

            const float* cb0 = cbk + (kg +   0) * CPAD;
            const float* cb1 = cbk + (kg +  64) * CPAD;
            const float* cb2 = cbk + (kg + 128) * CPAD;
            const float* cb3 = cbk + (kg + 192) * CPAD;
            const float* sb = s32t + rg * 8;

            for (int db = 0; db < DM_DIM; db += 4) {
                float ca[4], cb_[4], cc[4], cd[4];
                *(float4*)ca  = *(const float4*)(cb0 + db);
                *(float4*)cb_ = *(const float4*)(cb1 + db);
                *(float4*)cc  = *(const float4*)(cb2 + db);
                *(float4*)cd  = *(const float4*)(cb3 + db);
#pragma unroll
                for (int dd = 0; dd < 4; dd++) {
                    ulonglong2 sA = *(const ulonglong2*)(sb + (db + dd) * RP);      // rows 0-3
                    ulonglong2 sB = *(const ulonglong2*)(sb + (db + dd) * RP + 4);  // rows 4-7
                    u64 b0 = pack_dup(ca[dd]);
                    u64 b1 = pack_dup(cb_[dd]);
                    u64 b2 = pack_dup(cc[dd]);
                    u64 b3 = pack_dup(cd[dd]);
                    fma2(acc2[0][0], sA.x, b0); fma2(acc2[1][0], sA.y, b0);
                    fma2(acc2[2][0], sB.x, b0); fma2(acc2[3][0], sB.y, b0);
                    fma2(acc2[0][1], sA.x, b1); fma2(acc2[1][1], sA.y, b1);
                    fma2(acc2[2][1], sB.x, b1); fma2(acc2[3][1], sB.y, b1);
                    fma2(acc2[0][2], sA.x, b2); fma2(acc2[1][2], sA.y, b2);
                    fma2(acc2[2][2], sB.x, b2); fma2(acc2[3][2], sB.y, b2);
                    fma2(acc2[0][3], sA.x, b3); fma2(acc2[1][3], sA.y, b3);
                    fma2(acc2[2][3], sB.x, b3); fma2(acc2[3][3], sB.y, b3);
                }
            }
            // combine: dist = fl( fl(x2 - 2*xc) + c2 ), logit = -dist
#pragma unroll
            for (int p = 0; p < 4; p++) {
                float x2a = x2all[sc0 + rg * 8 + 2 * p];
                float x2b = x2all[sc0 + rg * 8 + 2 * p + 1];
#pragma unroll
                for (int j = 0; j < 4; j++) {
                    float2 xc = unpk(acc2[p][j]);
                    float c2v = c2s[kg + 64 * j];
                    lg[2 * p][j]     = -__fadd_rn(__fadd_rn(x2a, -(2.0f * xc.x)), c2v);
                    lg[2 * p + 1][j] = -__fadd_rn(__fadd_rn(x2b, -(2.0f * xc.y)), c2v);
                }
            }
        }

        // ---- per-row max/argmax via shuffles (lowest-index ties) ----
#pragma unroll
        for (int i = 0; i < 8; i++) {
            float v = lg[i][0]; int ix = kg;
#pragma unroll
            for (int j = 1; j < 4; j++) {
                if (lg[i][j] > v) { v = lg[i][j]; ix = kg + 64 * j; }
            }
#pragma unroll
            for (int off = 16; off; off >>= 1) {
                float ov = __shfl_down_sync(0xffffffffu, v, off);
                int   oi = __shfl_down_sync(0xffffffffu, ix, off);
                if (ov > v || (ov == v && oi < ix)) { v = ov; ix = oi; }
            }
            if (lane == 0) { wv[warp * 8 + i] = v; wi[warp * 8 + i] = ix; }
        }
        __syncthreads();
        if (tid < 32) {
            int i = tid & 7, w0 = (tid >> 3) * 2;
            float v0 = wv[w0 * 8 + i];       int i0 = wi[w0 * 8 + i];
            float v1 = wv[(w0 + 1) * 8 + i]; int i1 = wi[(w0 + 1) * 8 + i];
            if (v1 > v0 || (v1 == v0 && i1 < i0)) { v0 = v1; i0 = i1; }
            rowmax[tid] = v0;
            rowarg[tid] = i0;
            out[(size_t)(rS + tid) * M_SUB + m] = (float)i0;   // hard code
        }
        __syncthreads();

        // ---- exp + store probsT (pair-packed layout) + sum ----
#pragma unroll
        for (int i = 0; i < 8; i++) {
            float mx = rowmax[rg * 8 + i];
            float s = 0.f;
#pragma unroll
            for (int j = 0; j < 4; j++) {
                float e = __expf(lg[i][j] - mx);
                probsT[(kg + 64 * j) * PP + rg * 8 + i] = e;
                s += e;
            }
#pragma unroll
            for (int off = 16; off; off >>= 1) s += __shfl_down_sync(0xffffffffu, s, off);
            if (lane == 0) wsum[warp * 8 + i] = s;
        }
        __syncthreads();
        if (tid < 32) {
            int i = tid & 7, w0 = (tid >> 3) * 2;
            rowinv[tid] = 1.f / (wsum[w0 * 8 + i] + wsum[(w0 + 1) * 8 + i]);
        }
        __syncthreads();

        // ---- pass2: soft recon, thread = 2 row-pairs x 4 dims, FFMA2 ----
        {
            u64 sf[2][4];
#pragma unroll
            for (int p = 0; p < 2; p++)
#pragma unroll
                for (int t = 0; t < 4; t++) sf[p][t] = 0ull;

            for (int k0 = 0; k0 < K_CODES; k0 += 4) {
                float cm0[4], cm1[4], cm2[4], cm3[4];
                *(float4*)cm0 = *(const float4*)(cbk + (k0 + 0) * CPAD + d0);
                *(float4*)cm1 = *(const float4*)(cbk + (k0 + 1) * CPAD + d0);
                *(float4*)cm2 = *(const float4*)(cbk + (k0 + 2) * CPAD + d0);
                *(float4*)cm3 = *(const float4*)(cbk + (k0 + 3) * CPAD + d0);
#pragma unroll
                for (int kk = 0; kk < 4; kk++) {
                    const float* cf = (kk == 0) ? cm0 : (kk == 1) ? cm1 : (kk == 2) ? cm2 : cm3;
                    u64 p0 = *(const u64*)(probsT + (k0 + kk) * PP + r0);
                    u64 p1 = *(const u64*)(probsT + (k0 + kk) * PP + r0 + 2);
                    u64 b0 = pack_dup(cf[0]);
                    u64 b1 = pack_dup(cf[1]);
                    u64 b2 = pack_dup(cf[2]);
                    u64 b3 = pack_dup(cf[3]);
                    fma2(sf[0][0], p0, b0); fma2(sf[0][1], p0, b1);
                    fma2(sf[0][2], p0, b2); fma2(sf[0][3], p0, b3);
                    fma2(sf[1][0], p1, b0); fma2(sf[1][1], p1, b1);
                    fma2(sf[1][2], p1, b2); fma2(sf[1][3], p1, b3);
                }
            }
            // losses: sp from gmem (coalesced, L2-hot), hd from cbk
            float sp[4][4];
#pragma unroll
            for (int rr = 0; rr < 4; rr++)
                *(float4*)sp[rr] = *(const float4*)(g_xr + (size_t)(rS + r0 + rr) * D_DIM + m * DM_DIM + d0);
#pragma unroll
            for (int p = 0; p < 2; p++) {
                int ra = r0 + 2 * p, rb = ra + 1;
                float invA = rowinv[ra], invB = rowinv[rb];
                float hA[4], hB[4];
                *(float4*)hA = *(const float4*)(cbk + rowarg[ra] * CPAD + d0);
                *(float4*)hB = *(const float4*)(cbk + rowarg[rb] * CPAD + d0);
#pragma unroll
                for (int t = 0; t < 4; t++) {
                    float2 sv = unpk(sf[p][t]);
                    float softA = sv.x * invA, softB = sv.y * invB;
                    float spA = sp[2 * p][t], spB = sp[2 * p + 1][t];
                    float dsA = spA - softA, dsB = spB - softB;
                    float dhA = spA - hA[t], dhB = spB - hB[t];
                    float djA = softA - hA[t], djB = softB - hB[t];
                    aS += dsA * dsA + dsB * dsB;
                    aH += dhA * dhA + dhB * dhB;
                    aJ += djA * djA + djB * djB;
                }
            }
        }
        __syncthreads();
    }

    // block-reduce the 3 loss partials (reuse s32t as scratch: 768 floats)
    float* red = s32t;
    red[tid] = aS; red[256 + tid] = aH; red[512 + tid] = aJ;
    __syncthreads();
    for (int s = 128; s > 0; s >>= 1) {
        if (tid < s) {
            red[tid]       += red[tid + s];
            red[256 + tid] += red[256 + tid + s];
            red[512 + tid] += red[512 + tid + s];
        }
        __syncthreads();
    }
    if (tid == 0) {
        atomicAdd(&g_acc[0], (double)red[0]);
        atomicAdd(&g_acc[1], (double)red[256]);
        atomicAdd(&g_acc[2], (double)red[512]);
    }
}

// ---------------------------------------------------------------------------
// Kernel 4: combine loss
// ---------------------------------------------------------------------------
__global__ void finalize_kernel(float* out, int out_size) {
    if (threadIdx.x == 0) {
        double inv = 1.0 / ((double)N_ROWS * (double)DM_DIM);
        double loss = 0.1 * g_acc[0] * inv + g_acc[1] * inv + 0.1 * g_acc[2] * inv
                    + 0.01 * (g_acc[3] / ((double)D_DIM * (double)D_DIM));
        out[out_size - 1] = (float)loss;
    }
}

extern "C" void kernel_launch(void* const* d_in, const int* in_sizes, int n_in,
                              void* d_out, int out_size) {
    const float* x        = (const float*)d_in[0];
    const float* codebook = (const float*)d_in[1];
    const float* rotate   = (const float*)d_in[2];
    float* out = (float*)d_out;

    cudaFuncSetAttribute(pq_kernel, cudaFuncAttributeMaxDynamicSharedMemorySize, PQ_SMEM_BYTES);

    zero_acc_kernel<<<1, 32>>>();
    sgemm_kernel<<<dim3(D_DIM / GBN, N_ROWS / GBM), 256>>>(x, rotate);
    reg_kernel<<<D_DIM, 256>>>(rotate);
    pq_kernel<<<dim3(M_SUB, N_ROWS / ROWS_PB), 256, PQ_SMEM_BYTES>>>(codebook, out);
    finalize_kernel<<<1, 32>>>(out, out_size);
}

// round 9
// speedup vs baseline: 2.4181x; 1.0421x over previous
#include <cuda_runtime.h>
#include <cuda_bf16.h>
#include <math.h>

#define N_ROWS 131072
#define D_DIM  512
#define M_SUB  4
#define K_CODES 256
#define DM_DIM 128

typedef unsigned long long u64;
typedef unsigned int u32;

// ---- packed fp32x2 helpers (two independent IEEE-754 rn FMAs per instr) ----
__device__ __forceinline__ u64 pack_dup(float a) {
    u64 r; asm("mov.b64 %0, {%1, %1};" : "=l"(r) : "f"(a)); return r;
}
__device__ __forceinline__ void fma2(u64& d, u64 a, u64 b) {
    asm("fma.rn.f32x2 %0, %1, %2, %0;" : "+l"(d) : "l"(a), "l"(b));
}
__device__ __forceinline__ float2 unpk(u64 v) {
    float lo, hi; asm("mov.b64 {%0, %1}, %2;" : "=f"(lo), "=f"(hi) : "l"(v));
    return make_float2(lo, hi);
}
// bf16x2 (two probs of a row-pair) -> two fp32-duplicated u64 operands
__device__ __forceinline__ void bf2_dup(u32 pv, u64& plo, u64& phi) {
    u32 lo, hi;
    asm("shl.b32 %0, %1, 16;" : "=r"(lo) : "r"(pv));
    asm("and.b32 %0, %1, 0xFFFF0000;" : "=r"(hi) : "r"(pv));
    asm("mov.b64 %0, {%1, %1};" : "=l"(plo) : "r"(lo));
    asm("mov.b64 %0, {%1, %1};" : "=l"(phi) : "r"(hi));
}

// scratch: xr = x @ rotate  (268 MB) — static device array (no allocations allowed)
__device__ float g_xr[(size_t)N_ROWS * D_DIM];
__device__ double g_acc[4]; // 0:soft_d sum, 1:hard_d sum, 2:joint sum, 3:reg sum

__global__ void zero_acc_kernel() {
    if (threadIdx.x < 4) g_acc[threadIdx.x] = 0.0;
}

// ---------------------------------------------------------------------------
// Kernel 1: xr = x (131072x512) @ rotate (512x512), fp32 tiled SGEMM, FFMA2.
// BIT-EXACT CONTRACT: each output = single accumulator, strictly ascending k,
// IEEE rn FMA (f32x2 lanes are independent IEEE fp32 FMAs).
// ---------------------------------------------------------------------------
#define GBM 128
#define GBN 128
#define GBK 16

__global__ __launch_bounds__(256) void sgemm_kernel(const float* __restrict__ A,
                                                    const float* __restrict__ B) {
    __shared__ float As[GBK][GBM];   // transposed A tile
    __shared__ float Bs[GBK][GBN];
    const int tid = threadIdx.x;
    const int tx = tid & 15, ty = tid >> 4;
    const int R0 = blockIdx.y * GBM, C0 = blockIdx.x * GBN;

    u64 acc2[8][4];
#pragma unroll
    for (int i = 0; i < 8; i++)
#pragma unroll
        for (int j = 0; j < 4; j++) acc2[i][j] = 0ull;

    for (int k0 = 0; k0 < D_DIM; k0 += GBK) {
#pragma unroll
        for (int t = 0; t < 2; t++) {
            int f = tid + t * 256;
            int row = f >> 2, c4 = f & 3;
            float4 v = *(const float4*)(A + (size_t)(R0 + row) * D_DIM + k0 + c4 * 4);
            As[c4 * 4 + 0][row] = v.x;
            As[c4 * 4 + 1][row] = v.y;
            As[c4 * 4 + 2][row] = v.z;
            As[c4 * 4 + 3][row] = v.w;
        }
#pragma unroll
        for (int t = 0; t < 2; t++) {
            int f = tid + t * 256;
            int row = f >> 5, c4 = f & 31;
            float4 v = *(const float4*)(B + (size_t)(k0 + row) * D_DIM + C0 + c4 * 4);
            *(float4*)(&Bs[row][c4 * 4]) = v;
        }
        __syncthreads();

#pragma unroll
        for (int kk = 0; kk < GBK; kk++) {
            float a[8];
            *(float4*)(a)     = *(const float4*)(&As[kk][ty * 8]);
            *(float4*)(a + 4) = *(const float4*)(&As[kk][ty * 8 + 4]);
            ulonglong2 b01 = *(const ulonglong2*)(&Bs[kk][tx * 8]);
            ulonglong2 b23 = *(const ulonglong2*)(&Bs[kk][tx * 8 + 4]);
            u64 bb0 = b01.x, bb1 = b01.y, bb2 = b23.x, bb3 = b23.y;
#pragma unroll
            for (int i = 0; i < 8; i++) {
                u64 ad = pack_dup(a[i]);
                fma2(acc2[i][0], ad, bb0);
                fma2(acc2[i][1], ad, bb1);
                fma2(acc2[i][2], ad, bb2);
                fma2(acc2[i][3], ad, bb3);
            }
        }
        __syncthreads();
    }
#pragma unroll
    for (int i = 0; i < 8; i++) {
        float* orow = g_xr + (size_t)(R0 + ty * 8 + i) * D_DIM + C0 + tx * 8;
        ulonglong2 v0, v1;
        v0.x = acc2[i][0]; v0.y = acc2[i][1];
        v1.x = acc2[i][2]; v1.y = acc2[i][3];
        *(ulonglong2*)(orow)     = v0;
        *(ulonglong2*)(orow + 4) = v1;
    }
}

// ---------------------------------------------------------------------------
// Kernel 2: reg = sum((R R^T - I)^2)  -> g_acc[3]   (loss-only, tolerance loose)
// ---------------------------------------------------------------------------
__global__ __launch_bounds__(256) void reg_kernel(const float* __restrict__ R) {
    __shared__ float ri[D_DIM];
    __shared__ float part[8];
    const int i = blockIdx.x;
    const int tid = threadIdx.x;
    for (int d = tid; d < D_DIM; d += 256) ri[d] = R[(size_t)i * D_DIM + d];
    __syncthreads();

    const int warp = tid >> 5, lane = tid & 31;
    float accum = 0.f;
    for (int j = warp; j < D_DIM; j += 8) {
        const float* rj = R + (size_t)j * D_DIM;
        float dot = 0.f;
#pragma unroll 4
        for (int k = lane; k < D_DIM; k += 32) dot += ri[k] * rj[k];
#pragma unroll
        for (int off = 16; off; off >>= 1) dot += __shfl_down_sync(0xffffffffu, dot, off);
        if (lane == 0) {
            float v = dot - (j == i ? 1.f : 0.f);
            accum += v * v;
        }
    }
    if (lane == 0) part[warp] = accum;
    __syncthreads();
    if (tid == 0) {
        float s = 0.f;
#pragma unroll
        for (int w = 0; w < 8; w++) s += part[w];
        atomicAdd(&g_acc[3], (double)s);
    }
}

// ---------------------------------------------------------------------------
// Kernel 3: fused distance / softmax / argmax / soft-recon / losses
// 512 threads (16 warps), grid (M, 512), 256 rows per block, SUPER=64.
//
// BIT-EXACT logits path (identical arithmetic to rounds 5/7/8):
//   x2   = sum_d fl(s*s) sequential ascending;  c2 same
//   xc   = single-accumulator IEEE-rn FMA chain, ascending d
//   dist = fl( fl(x2 - 2*xc) + c2 ),  logits = -dist
//   argmax lowest-index tie-break
//
// pass1: FFMA2, thread = 8 rows (4 pairs) x 4 codes. splits d-major s32t[d][64].
// probs: bf16 row-pairs, probsT[k][66 halves]  (loss-only precision).
// pass2: FFMA2 packed over DIM pairs; thread = 4 rows x 4 dims, all 256 codes.
// ---------------------------------------------------------------------------
#define ROWS_PB 256
#define SUPER 64
#define CPAD 132
#define RP 64
#define PPH 66   /* bf16 elements per probsT row (64 rows + pad); PPH/2 odd -> conflict-free */
#define PQ_SMEM_FLOATS (K_CODES * CPAD + 256 + 256 + 128 * RP + (K_CODES * PPH) / 2 + 128 + 128 + 64 + 64 + 128 + 64)
#define PQ_SMEM_BYTES (PQ_SMEM_FLOATS * 4)

__global__ __launch_bounds__(512) void pq_kernel(const float* __restrict__ codebook,
                                                 float* __restrict__ out) {
    extern __shared__ float sm[];
    float* cbk    = sm;                          // [256][132] codebook k-major
    float* c2s    = cbk + K_CODES * CPAD;        // [256]
    float* x2all  = c2s + 256;                   // [256]
    float* s32t   = x2all + 256;                 // [128][64] splits d-major
    __nv_bfloat16* probsT = (__nv_bfloat16*)(s32t + 128 * RP); // [256][66] bf16
    float* wv     = (float*)(s32t + 128 * RP) + (K_CODES * PPH) / 2; // [16][8]
    float* wsum   = wv + 128;                    // [16][8]
    float* rowmax = wsum + 128;                  // [64]
    float* rowinv = rowmax + 64;                 // [64]
    int*   wi     = (int*)(rowinv + 64);         // [16][8]
    int*   rowarg = wi + 128;                    // [64]

    const int m   = blockIdx.x;
    const int nb  = blockIdx.y;
    const int tid = threadIdx.x;
    const int lane = tid & 31, warp = tid >> 5;
    const int base = nb * ROWS_PB;

    // stage codebook[m] k-major
    const float* cbm = codebook + (size_t)m * K_CODES * DM_DIM;
    for (int idx = tid; idx < K_CODES * (DM_DIM / 4); idx += 512) {
        int k = idx >> 5, d4 = idx & 31;
        *(float4*)(cbk + k * CPAD + d4 * 4) = *(const float4*)(cbm + (size_t)k * DM_DIM + d4 * 4);
    }
    __syncthreads();
    if (tid < 256) {   // c2[k]: sequential ascending, rounded mul then add
        const float* ck = cbk + tid * CPAD;
        float s = 0.f;
        for (int d = 0; d < DM_DIM; d++) {
            float c = ck[d];
            s = __fadd_rn(s, __fmul_rn(c, c));
        }
        c2s[tid] = s;
    } else {           // x2 for all 256 rows: strictly sequential ascending d
        int r = tid - 256;
        const float* xp = g_xr + (size_t)(base + r) * D_DIM + m * DM_DIM;
        float s = 0.f;
        for (int d = 0; d < DM_DIM; d++) {
            float v = xp[d];
            s = __fadd_rn(s, __fmul_rn(v, v));
        }
        x2all[r] = s;
    }
    __syncthreads();

    float aS = 0.f, aH = 0.f, aJ = 0.f;

    const int kg = tid & 63, rg = tid >> 6;      // pass1: codes kg+64j, rows rg*8..+7
    const int dgq = tid & 31, rq = tid >> 5;     // pass2: dims dgq*4..+3, rows rq*4..+3
    const int d0 = dgq * 4;

    for (int sc0 = 0; sc0 < ROWS_PB; sc0 += SUPER) {
        const int rS = base + sc0;

        // ---- stage splits d-major: s32t[d][row], conflict-free scatter ----
        {
            int row = tid & 63, dq = tid >> 6;   // dq 0..7 -> 16 d's each
            const float* xp = g_xr + (size_t)(rS + row) * D_DIM + m * DM_DIM + dq * 16;
#pragma unroll
            for (int t = 0; t < 4; t++) {
                float4 v = *(const float4*)(xp + t * 4);
                int d = dq * 16 + t * 4;
                s32t[(d + 0) * RP + row] = v.x;
                s32t[(d + 1) * RP + row] = v.y;
                s32t[(d + 2) * RP + row] = v.z;
                s32t[(d + 3) * RP + row] = v.w;
            }
        }
        __syncthreads();

        // ---- pass1: xc for 8 rows (4 pairs) x 4 codes per thread, FFMA2 ----
        float lg[8][4];
        {
            u64 acc2[4][4];
#pragma unroll
            for (int p = 0; p < 4; p++)
#pragma unroll
                for (int j = 0; j < 4; j++) acc2[p][j] = 0ull;

            const float* cb0 = cbk + (kg +   0) * CPAD;
            const float* cb1 = cbk + (kg +  64) * CPAD;
            const float* cb2 = cbk + (kg + 128) * CPAD;
            const float* cb3 = cbk + (kg + 192) * CPAD;
            const float* sb = s32t + rg * 8;

            for (int db = 0; db < DM_DIM; db += 4) {
                float ca[4], cb_[4], cc[4], cd[4];
                *(float4*)ca  = *(const float4*)(cb0 + db);
                *(float4*)cb_ = *(const float4*)(cb1 + db);
                *(float4*)cc  = *(const float4*)(cb2 + db);
                *(float4*)cd  = *(const float4*)(cb3 + db);
#pragma unroll
                for (int dd = 0; dd < 4; dd++) {
                    ulonglong2 sA = *(const ulonglong2*)(sb + (db + dd) * RP);      // rows 0-3
                    ulonglong2 sB = *(const ulonglong2*)(sb + (db + dd) * RP + 4);  // rows 4-7
                    u64 b0 = pack_dup(ca[dd]);
                    u64 b1 = pack_dup(cb_[dd]);
                    u64 b2 = pack_dup(cc[dd]);
                    u64 b3 = pack_dup(cd[dd]);
                    fma2(acc2[0][0], sA.x, b0); fma2(acc2[1][0], sA.y, b0);
                    fma2(acc2[2][0], sB.x, b0); fma2(acc2[3][0], sB.y, b0);
                    fma2(acc2[0][1], sA.x, b1); fma2(acc2[1][1], sA.y, b1);
                    fma2(acc2[2][1], sB.x, b1); fma2(acc2[3][1], sB.y, b1);
                    fma2(acc2[0][2], sA.x, b2); fma2(acc2[1][2], sA.y, b2);
                    fma2(acc2[2][2], sB.x, b2); fma2(acc2[3][2], sB.y, b2);
                    fma2(acc2[0][3], sA.x, b3); fma2(acc2[1][3], sA.y, b3);
                    fma2(acc2[2][3], sB.x, b3); fma2(acc2[3][3], sB.y, b3);
                }
            }
            // combine: dist = fl( fl(x2 - 2*xc) + c2 ), logit = -dist
#pragma unroll
            for (int p = 0; p < 4; p++) {
                float x2a = x2all[sc0 + rg * 8 + 2 * p];
                float x2b = x2all[sc0 + rg * 8 + 2 * p + 1];
#pragma unroll
                for (int j = 0; j < 4; j++) {
                    float2 xc = unpk(acc2[p][j]);
                    float c2v = c2s[kg + 64 * j];
                    lg[2 * p][j]     = -__fadd_rn(__fadd_rn(x2a, -(2.0f * xc.x)), c2v);
                    lg[2 * p + 1][j] = -__fadd_rn(__fadd_rn(x2b, -(2.0f * xc.y)), c2v);
                }
            }
        }

        // ---- per-row max/argmax via shuffles (lowest-index ties) ----
#pragma unroll
        for (int i = 0; i < 8; i++) {
            float v = lg[i][0]; int ix = kg;
#pragma unroll
            for (int j = 1; j < 4; j++) {
                if (lg[i][j] > v) { v = lg[i][j]; ix = kg + 64 * j; }
            }
#pragma unroll
            for (int off = 16; off; off >>= 1) {
                float ov = __shfl_down_sync(0xffffffffu, v, off);
                int   oi = __shfl_down_sync(0xffffffffu, ix, off);
                if (ov > v || (ov == v && oi < ix)) { v = ov; ix = oi; }
            }
            if (lane == 0) { wv[warp * 8 + i] = v; wi[warp * 8 + i] = ix; }
        }
        __syncthreads();
        if (tid < 64) {
            int i = tid & 7, w0 = (tid >> 3) * 2;
            float v0 = wv[w0 * 8 + i];       int i0 = wi[w0 * 8 + i];
            float v1 = wv[(w0 + 1) * 8 + i]; int i1 = wi[(w0 + 1) * 8 + i];
            if (v1 > v0 || (v1 == v0 && i1 < i0)) { v0 = v1; i0 = i1; }
            rowmax[tid] = v0;
            rowarg[tid] = i0;
            out[(size_t)(rS + tid) * M_SUB + m] = (float)i0;   // hard code
        }
        __syncthreads();

        // ---- exp (in place), row sums, bf16 pair-packed store ----
#pragma unroll
        for (int i = 0; i < 8; i++) {
            float mx = rowmax[rg * 8 + i];
            float s = 0.f;
#pragma unroll
            for (int j = 0; j < 4; j++) {
                float e = __expf(lg[i][j] - mx);
                lg[i][j] = e;
                s += e;
            }
#pragma unroll
            for (int off = 16; off; off >>= 1) s += __shfl_down_sync(0xffffffffu, s, off);
            if (lane == 0) wsum[warp * 8 + i] = s;
        }
#pragma unroll
        for (int j = 0; j < 4; j++) {
            int k = kg + 64 * j;
#pragma unroll
            for (int p = 0; p < 4; p++) {
                __nv_bfloat162 h = __floats2bfloat162_rn(lg[2 * p][j], lg[2 * p + 1][j]);
                *(__nv_bfloat162*)(probsT + k * PPH + rg * 8 + 2 * p) = h;
            }
        }
        __syncthreads();
        if (tid < 64) {
            int i = tid & 7, w0 = (tid >> 3) * 2;
            rowinv[tid] = 1.f / (wsum[w0 * 8 + i] + wsum[(w0 + 1) * 8 + i]);
        }
        __syncthreads();

        // ---- pass2: soft recon, FFMA2 packed over dim pairs ----
        {
            u64 sf[4][2];   // [row 0..3][dim-pair 0..1]
#pragma unroll
            for (int r = 0; r < 4; r++) { sf[r][0] = 0ull; sf[r][1] = 0ull; }

            const u32* prb = (const u32*)(probsT + rq * 4);
            const float* cbd = cbk + d0;

#pragma unroll 4
            for (int k = 0; k < K_CODES; k++) {
                ulonglong2 cv = *(const ulonglong2*)(cbd + k * CPAD);  // dims d0..d0+3
                u32 p01 = prb[k * (PPH / 2)];
                u32 p23 = prb[k * (PPH / 2) + 1];
                u64 a0, a1, a2, a3;
                bf2_dup(p01, a0, a1);
                bf2_dup(p23, a2, a3);
                fma2(sf[0][0], a0, cv.x); fma2(sf[0][1], a0, cv.y);
                fma2(sf[1][0], a1, cv.x); fma2(sf[1][1], a1, cv.y);
                fma2(sf[2][0], a2, cv.x); fma2(sf[2][1], a2, cv.y);
                fma2(sf[3][0], a3, cv.x); fma2(sf[3][1], a3, cv.y);
            }
            // losses: sp from gmem (coalesced), hd from cbk
#pragma unroll
            for (int r = 0; r < 4; r++) {
                int lr = rq * 4 + r;
                float inv = rowinv[lr];
                float sp[4], hd[4];
                *(float4*)sp = *(const float4*)(g_xr + (size_t)(rS + lr) * D_DIM + m * DM_DIM + d0);
                *(float4*)hd = *(const float4*)(cbk + rowarg[lr] * CPAD + d0);
                float2 s01 = unpk(sf[r][0]);
                float2 s23 = unpk(sf[r][1]);
                float soft[4] = { s01.x * inv, s01.y * inv, s23.x * inv, s23.y * inv };
#pragma unroll
                for (int t = 0; t < 4; t++) {
                    float ds = sp[t] - soft[t];
                    float dh = sp[t] - hd[t];
                    float dj = soft[t] - hd[t];
                    aS += ds * ds;
                    aH += dh * dh;
                    aJ += dj * dj;
                }
            }
        }
        __syncthreads();
    }

    // block-reduce the 3 loss partials (reuse s32t as scratch: 1536 floats)
    float* red = s32t;
    red[tid] = aS; red[512 + tid] = aH; red[1024 + tid] = aJ;
    __syncthreads();
    for (int s = 256; s > 0; s >>= 1) {
        if (tid < s) {
            red[tid]        += red[tid + s];
            red[512 + tid]  += red[512 + tid + s];
            red[1024 + tid] += red[1024 + tid + s];
        }
        __syncthreads();
    }
    if (tid == 0) {
        atomicAdd(&g_acc[0], (double)red[0]);
        atomicAdd(&g_acc[1], (double)red[512]);
        atomicAdd(&g_acc[2], (double)red[1024]);
    }
}

// ---------------------------------------------------------------------------
// Kernel 4: combine loss
// ---------------------------------------------------------------------------
__global__ void finalize_kernel(float* out, int out_size) {
    if (threadIdx.x == 0) {
        double inv = 1.0 / ((double)N_ROWS * (double)DM_DIM);
        double loss = 0.1 * g_acc[0] * inv + g_acc[1] * inv + 0.1 * g_acc[2] * inv
                    + 0.01 * (g_acc[3] / ((double)D_DIM * (double)D_DIM));
        out[out_size - 1] = (float)loss;
    }
}

extern "C" void kernel_launch(void* const* d_in, const int* in_sizes, int n_in,
                              void* d_out, int out_size) {
    const float* x        = (const float*)d_in[0];
    const float* codebook = (const float*)d_in[1];
    const float* rotate   = (const float*)d_in[2];
    float* out = (float*)d_out;

    cudaFuncSetAttribute(pq_kernel, cudaFuncAttributeMaxDynamicSharedMemorySize, PQ_SMEM_BYTES);

    zero_acc_kernel<<<1, 32>>>();
    sgemm_kernel<<<dim3(D_DIM / GBN, N_ROWS / GBM), 256>>>(x, rotate);
    reg_kernel<<<D_DIM, 256>>>(rotate);
    pq_kernel<<<dim3(M_SUB, N_ROWS / ROWS_PB), 512, PQ_SMEM_BYTES>>>(codebook, out);
    finalize_kernel<<<1, 32>>>(out, out_size);
}

// round 10
// speedup vs baseline: 2.9776x; 1.2314x over previous
#include <cuda_runtime.h>
#include <math.h>

#define N_ROWS 131072
#define D_DIM  512
#define M_SUB  4
#define K_CODES 256
#define DM_DIM 128

typedef unsigned long long u64;
typedef unsigned int u32;

// ---- packed fp32x2 helpers (two independent IEEE-754 rn FMAs per instr) ----
__device__ __forceinline__ u64 pack_dup(float a) {
    u64 r; asm("mov.b64 %0, {%1, %1};" : "=l"(r) : "f"(a)); return r;
}
__device__ __forceinline__ void fma2(u64& d, u64 a, u64 b) {
    asm("fma.rn.f32x2 %0, %1, %2, %0;" : "+l"(d) : "l"(a), "l"(b));
}
__device__ __forceinline__ float2 unpk(u64 v) {
    float lo, hi; asm("mov.b64 {%0, %1}, %2;" : "=f"(lo), "=f"(hi) : "l"(v));
    return make_float2(lo, hi);
}

// scratch: xr = x @ rotate  (268 MB) — static device array (no allocations allowed)
__device__ float g_xr[(size_t)N_ROWS * D_DIM];
__device__ double g_acc[4]; // 0:soft_d sum, 1:hard_d sum, 2:joint sum, 3:reg sum

__global__ void zero_acc_kernel() {
    if (threadIdx.x < 4) g_acc[threadIdx.x] = 0.0;
}

// ---------------------------------------------------------------------------
// Kernel 1: xr = x (131072x512) @ rotate (512x512), fp32 tiled SGEMM, FFMA2.
// BIT-EXACT CONTRACT: each output = single accumulator, strictly ascending k,
// IEEE rn FMA (f32x2 lanes are independent IEEE fp32 FMAs).
// ---------------------------------------------------------------------------
#define GBM 128
#define GBN 128
#define GBK 16

__global__ __launch_bounds__(256) void sgemm_kernel(const float* __restrict__ A,
                                                    const float* __restrict__ B) {
    __shared__ float As[GBK][GBM];   // transposed A tile
    __shared__ float Bs[GBK][GBN];
    const int tid = threadIdx.x;
    const int tx = tid & 15, ty = tid >> 4;
    const int R0 = blockIdx.y * GBM, C0 = blockIdx.x * GBN;

    u64 acc2[8][4];
#pragma unroll
    for (int i = 0; i < 8; i++)
#pragma unroll
        for (int j = 0; j < 4; j++) acc2[i][j] = 0ull;

    for (int k0 = 0; k0 < D_DIM; k0 += GBK) {
#pragma unroll
        for (int t = 0; t < 2; t++) {
            int f = tid + t * 256;
            int row = f >> 2, c4 = f & 3;
            float4 v = *(const float4*)(A + (size_t)(R0 + row) * D_DIM + k0 + c4 * 4);
            As[c4 * 4 + 0][row] = v.x;
            As[c4 * 4 + 1][row] = v.y;
            As[c4 * 4 + 2][row] = v.z;
            As[c4 * 4 + 3][row] = v.w;
        }
#pragma unroll
        for (int t = 0; t < 2; t++) {
            int f = tid + t * 256;
            int row = f >> 5, c4 = f & 31;
            float4 v = *(const float4*)(B + (size_t)(k0 + row) * D_DIM + C0 + c4 * 4);
            *(float4*)(&Bs[row][c4 * 4]) = v;
        }
        __syncthreads();

#pragma unroll
        for (int kk = 0; kk < GBK; kk++) {
            float a[8];
            *(float4*)(a)     = *(const float4*)(&As[kk][ty * 8]);
            *(float4*)(a + 4) = *(const float4*)(&As[kk][ty * 8 + 4]);
            ulonglong2 b01 = *(const ulonglong2*)(&Bs[kk][tx * 8]);
            ulonglong2 b23 = *(const ulonglong2*)(&Bs[kk][tx * 8 + 4]);
            u64 bb0 = b01.x, bb1 = b01.y, bb2 = b23.x, bb3 = b23.y;
#pragma unroll
            for (int i = 0; i < 8; i++) {
                u64 ad = pack_dup(a[i]);
                fma2(acc2[i][0], ad, bb0);
                fma2(acc2[i][1], ad, bb1);
                fma2(acc2[i][2], ad, bb2);
                fma2(acc2[i][3], ad, bb3);
            }
        }
        __syncthreads();
    }
#pragma unroll
    for (int i = 0; i < 8; i++) {
        float* orow = g_xr + (size_t)(R0 + ty * 8 + i) * D_DIM + C0 + tx * 8;
        ulonglong2 v0, v1;
        v0.x = acc2[i][0]; v0.y = acc2[i][1];
        v1.x = acc2[i][2]; v1.y = acc2[i][3];
        *(ulonglong2*)(orow)     = v0;
        *(ulonglong2*)(orow + 4) = v1;
    }
}

// ---------------------------------------------------------------------------
// Kernel 2: reg = sum((R R^T - I)^2)  -> g_acc[3]   (loss-only, tolerance loose)
// ---------------------------------------------------------------------------
__global__ __launch_bounds__(256) void reg_kernel(const float* __restrict__ R) {
    __shared__ float ri[D_DIM];
    __shared__ float part[8];
    const int i = blockIdx.x;
    const int tid = threadIdx.x;
    for (int d = tid; d < D_DIM; d += 256) ri[d] = R[(size_t)i * D_DIM + d];
    __syncthreads();

    const int warp = tid >> 5, lane = tid & 31;
    float accum = 0.f;
    for (int j = warp; j < D_DIM; j += 8) {
        const float* rj = R + (size_t)j * D_DIM;
        float dot = 0.f;
#pragma unroll 4
        for (int k = lane; k < D_DIM; k += 32) dot += ri[k] * rj[k];
#pragma unroll
        for (int off = 16; off; off >>= 1) dot += __shfl_down_sync(0xffffffffu, dot, off);
        if (lane == 0) {
            float v = dot - (j == i ? 1.f : 0.f);
            accum += v * v;
        }
    }
    if (lane == 0) part[warp] = accum;
    __syncthreads();
    if (tid == 0) {
        float s = 0.f;
#pragma unroll
        for (int w = 0; w < 8; w++) s += part[w];
        atomicAdd(&g_acc[3], (double)s);
    }
}

// ---------------------------------------------------------------------------
// Kernel 3: fused distance / softmax / argmax / SPARSE soft-recon / losses
// 512 threads (16 warps), grid (M, 512), 256 rows per block, SUPER=64.
//
// BIT-EXACT logits path (identical arithmetic to rounds 5/7/8/9):
//   x2   = sum_d fl(s*s) sequential ascending;  c2 same
//   xc   = single-accumulator IEEE-rn FMA chain, ascending d
//   dist = fl( fl(x2 - 2*xc) + c2 ),  logits = -dist
//   argmax lowest-index tie-break
//
// Softmax is near-one-hot (logit std ~2*sqrt(x2) ~ 500 >> window): soft recon
// uses a per-row sparse list of codes with lg - max > -35 (dropped mass
// < 256*e^-35 ~ 2e-13); Z is still the exact full 256-term sum.
// ---------------------------------------------------------------------------
#define ROWS_PB 256
#define SUPER 64
#define CPAD 132
#define RP 64
#define MAXSLOT 16
#define LIST_THRESH -35.0f
#define PQ_SMEM_FLOATS (K_CODES * CPAD + 256 + 256 + 128 * RP + SUPER * (MAXSLOT + 1) * 2 + 128 + 128 + 64 + 64 + 128 + 64 + 64)
#define PQ_SMEM_BYTES (PQ_SMEM_FLOATS * 4)

__global__ __launch_bounds__(512) void pq_kernel(const float* __restrict__ codebook,
                                                 float* __restrict__ out) {
    extern __shared__ float sm[];
    float* cbk    = sm;                          // [256][132] codebook k-major
    float* c2s    = cbk + K_CODES * CPAD;        // [256]
    float* x2all  = c2s + 256;                   // [256]
    float* s32t   = x2all + 256;                 // [128][64] splits d-major
    float2* listEK = (float2*)(s32t + 128 * RP); // [64][17] (e, k-as-float-bits)
    float* wv     = (float*)(listEK) + SUPER * (MAXSLOT + 1) * 2; // [16][8]
    float* wsum   = wv + 128;                    // [16][8]
    float* rowmax = wsum + 128;                  // [64]
    float* rowinv = rowmax + 64;                 // [64]
    int*   wi     = (int*)(rowinv + 64);         // [16][8]
    int*   rowarg = wi + 128;                    // [64]
    int*   scnt   = rowarg + 64;                 // [64]

    const int m   = blockIdx.x;
    const int nb  = blockIdx.y;
    const int tid = threadIdx.x;
    const int lane = tid & 31, warp = tid >> 5;
    const int base = nb * ROWS_PB;

    // stage codebook[m] k-major
    const float* cbm = codebook + (size_t)m * K_CODES * DM_DIM;
    for (int idx = tid; idx < K_CODES * (DM_DIM / 4); idx += 512) {
        int k = idx >> 5, d4 = idx & 31;
        *(float4*)(cbk + k * CPAD + d4 * 4) = *(const float4*)(cbm + (size_t)k * DM_DIM + d4 * 4);
    }
    __syncthreads();
    if (tid < 256) {   // c2[k]: sequential ascending, rounded mul then add
        const float* ck = cbk + tid * CPAD;
        float s = 0.f;
        for (int d = 0; d < DM_DIM; d++) {
            float c = ck[d];
            s = __fadd_rn(s, __fmul_rn(c, c));
        }
        c2s[tid] = s;
    } else {           // x2 for all 256 rows: strictly sequential ascending d
        int r = tid - 256;
        const float* xp = g_xr + (size_t)(base + r) * D_DIM + m * DM_DIM;
        float s = 0.f;
        for (int d = 0; d < DM_DIM; d++) {
            float v = xp[d];
            s = __fadd_rn(s, __fmul_rn(v, v));
        }
        x2all[r] = s;
    }
    __syncthreads();

    float aS = 0.f, aH = 0.f, aJ = 0.f;

    const int kg = tid & 63, rg = tid >> 6;      // pass1: codes kg+64j, rows rg*8..+7

    for (int sc0 = 0; sc0 < ROWS_PB; sc0 += SUPER) {
        const int rS = base + sc0;

        // ---- stage splits d-major: s32t[d][row]; zero the sparse counters ----
        {
            int row = tid & 63, dq = tid >> 6;   // dq 0..7 -> 16 d's each
            const float* xp = g_xr + (size_t)(rS + row) * D_DIM + m * DM_DIM + dq * 16;
#pragma unroll
            for (int t = 0; t < 4; t++) {
                float4 v = *(const float4*)(xp + t * 4);
                int d = dq * 16 + t * 4;
                s32t[(d + 0) * RP + row] = v.x;
                s32t[(d + 1) * RP + row] = v.y;
                s32t[(d + 2) * RP + row] = v.z;
                s32t[(d + 3) * RP + row] = v.w;
            }
            if (tid < SUPER) scnt[tid] = 0;
        }
        __syncthreads();

        // ---- pass1: xc for 8 rows (4 pairs) x 4 codes per thread, FFMA2 ----
        float lg[8][4];
        {
            u64 acc2[4][4];
#pragma unroll
            for (int p = 0; p < 4; p++)
#pragma unroll
                for (int j = 0; j < 4; j++) acc2[p][j] = 0ull;

            const float* cb0 = cbk + (kg +   0) * CPAD;
            const float* cb1 = cbk + (kg +  64) * CPAD;
            const float* cb2 = cbk + (kg + 128) * CPAD;
            const float* cb3 = cbk + (kg + 192) * CPAD;
            const float* sb = s32t + rg * 8;

            for (int db = 0; db < DM_DIM; db += 4) {
                float ca[4], cb_[4], cc[4], cd[4];
                *(float4*)ca  = *(const float4*)(cb0 + db);
                *(float4*)cb_ = *(const float4*)(cb1 + db);
                *(float4*)cc  = *(const float4*)(cb2 + db);
                *(float4*)cd  = *(const float4*)(cb3 + db);
#pragma unroll
                for (int dd = 0; dd < 4; dd++) {
                    ulonglong2 sA = *(const ulonglong2*)(sb + (db + dd) * RP);      // rows 0-3
                    ulonglong2 sB = *(const ulonglong2*)(sb + (db + dd) * RP + 4);  // rows 4-7
                    u64 b0 = pack_dup(ca[dd]);
                    u64 b1 = pack_dup(cb_[dd]);
                    u64 b2 = pack_dup(cc[dd]);
                    u64 b3 = pack_dup(cd[dd]);
                    fma2(acc2[0][0], sA.x, b0); fma2(acc2[1][0], sA.y, b0);
                    fma2(acc2[2][0], sB.x, b0); fma2(acc2[3][0], sB.y, b0);
                    fma2(acc2[0][1], sA.x, b1); fma2(acc2[1][1], sA.y, b1);
                    fma2(acc2[2][1], sB.x, b1); fma2(acc2[3][1], sB.y, b1);
                    fma2(acc2[0][2], sA.x, b2); fma2(acc2[1][2], sA.y, b2);
                    fma2(acc2[2][2], sB.x, b2); fma2(acc2[3][2], sB.y, b2);
                    fma2(acc2[0][3], sA.x, b3); fma2(acc2[1][3], sA.y, b3);
                    fma2(acc2[2][3], sB.x, b3); fma2(acc2[3][3], sB.y, b3);
                }
            }
            // combine: dist = fl( fl(x2 - 2*xc) + c2 ), logit = -dist
#pragma unroll
            for (int p = 0; p < 4; p++) {
                float x2a = x2all[sc0 + rg * 8 + 2 * p];
                float x2b = x2all[sc0 + rg * 8 + 2 * p + 1];
#pragma unroll
                for (int j = 0; j < 4; j++) {
                    float2 xc = unpk(acc2[p][j]);
                    float c2v = c2s[kg + 64 * j];
                    lg[2 * p][j]     = -__fadd_rn(__fadd_rn(x2a, -(2.0f * xc.x)), c2v);
                    lg[2 * p + 1][j] = -__fadd_rn(__fadd_rn(x2b, -(2.0f * xc.y)), c2v);
                }
            }
        }

        // ---- per-row max/argmax via shuffles (lowest-index ties) ----
#pragma unroll
        for (int i = 0; i < 8; i++) {
            float v = lg[i][0]; int ix = kg;
#pragma unroll
            for (int j = 1; j < 4; j++) {
                if (lg[i][j] > v) { v = lg[i][j]; ix = kg + 64 * j; }
            }
#pragma unroll
            for (int off = 16; off; off >>= 1) {
                float ov = __shfl_down_sync(0xffffffffu, v, off);
                int   oi = __shfl_down_sync(0xffffffffu, ix, off);
                if (ov > v || (ov == v && oi < ix)) { v = ov; ix = oi; }
            }
            if (lane == 0) { wv[warp * 8 + i] = v; wi[warp * 8 + i] = ix; }
        }
        __syncthreads();
        if (tid < 64) {
            int i = tid & 7, w0 = (tid >> 3) * 2;
            float v0 = wv[w0 * 8 + i];       int i0 = wi[w0 * 8 + i];
            float v1 = wv[(w0 + 1) * 8 + i]; int i1 = wi[(w0 + 1) * 8 + i];
            if (v1 > v0 || (v1 == v0 && i1 < i0)) { v0 = v1; i0 = i1; }
            rowmax[tid] = v0;
            rowarg[tid] = i0;
            out[(size_t)(rS + tid) * M_SUB + m] = (float)i0;   // hard code
        }
        __syncthreads();

        // ---- exp + exact full Z + sparse list build ----
#pragma unroll
        for (int i = 0; i < 8; i++) {
            int r = rg * 8 + i;
            float mx = rowmax[r];
            float s = 0.f;
#pragma unroll
            for (int j = 0; j < 4; j++) {
                float lsh = lg[i][j] - mx;
                float e = __expf(lsh);
                s += e;
                if (lsh > LIST_THRESH) {
                    int slot = atomicAdd(&scnt[r], 1);
                    if (slot < MAXSLOT) {
                        listEK[r * (MAXSLOT + 1) + slot] =
                            make_float2(e, __int_as_float(kg + 64 * j));
                    }
                }
            }
#pragma unroll
            for (int off = 16; off; off >>= 1) s += __shfl_down_sync(0xffffffffu, s, off);
            if (lane == 0) wsum[warp * 8 + i] = s;
        }
        __syncthreads();
        if (tid < 64) {
            int i = tid & 7, w0 = (tid >> 3) * 2;
            rowinv[tid] = 1.f / (wsum[w0 * 8 + i] + wsum[(w0 + 1) * 8 + i]);
        }
        __syncthreads();

        // ---- sparse soft recon + losses: warp -> 4 rows, lane -> 4 dims ----
        {
            const int d0 = lane * 4;
#pragma unroll
            for (int rr = 0; rr < 4; rr++) {
                int r = warp * 4 + rr;
                int cnt = scnt[r]; if (cnt > MAXSLOT) cnt = MAXSLOT;
                float sx = 0.f, sy = 0.f, sz = 0.f, sw = 0.f;
                for (int s = 0; s < cnt; s++) {
                    float2 ek = listEK[r * (MAXSLOT + 1) + s];
                    int k = __float_as_int(ek.y);
                    float4 cv = *(const float4*)(cbk + k * CPAD + d0);
                    sx += ek.x * cv.x;
                    sy += ek.x * cv.y;
                    sz += ek.x * cv.z;
                    sw += ek.x * cv.w;
                }
                float inv = rowinv[r];
                float4 sp = *(const float4*)(g_xr + (size_t)(rS + r) * D_DIM + m * DM_DIM + d0);
                float4 hd = *(const float4*)(cbk + rowarg[r] * CPAD + d0);
                float soft[4] = { sx * inv, sy * inv, sz * inv, sw * inv };
                float spv[4] = { sp.x, sp.y, sp.z, sp.w };
                float hdv[4] = { hd.x, hd.y, hd.z, hd.w };
#pragma unroll
                for (int t = 0; t < 4; t++) {
                    float ds = spv[t] - soft[t];
                    float dh = spv[t] - hdv[t];
                    float dj = soft[t] - hdv[t];
                    aS += ds * ds;
                    aH += dh * dh;
                    aJ += dj * dj;
                }
            }
        }
        __syncthreads();
    }

    // block-reduce the 3 loss partials (reuse s32t as scratch: 1536 floats)
    float* red = s32t;
    red[tid] = aS; red[512 + tid] = aH; red[1024 + tid] = aJ;
    __syncthreads();
    for (int s = 256; s > 0; s >>= 1) {
        if (tid < s) {
            red[tid]        += red[tid + s];
            red[512 + tid]  += red[512 + tid + s];
            red[1024 + tid] += red[1024 + tid + s];
        }
        __syncthreads();
    }
    if (tid == 0) {
        atomicAdd(&g_acc[0], (double)red[0]);
        atomicAdd(&g_acc[1], (double)red[512]);
        atomicAdd(&g_acc[2], (double)red[1024]);
    }
}

// ---------------------------------------------------------------------------
// Kernel 4: combine loss
// ---------------------------------------------------------------------------
__global__ void finalize_kernel(float* out, int out_size) {
    if (threadIdx.x == 0) {
        double inv = 1.0 / ((double)N_ROWS * (double)DM_DIM);
        double loss = 0.1 * g_acc[0] * inv + g_acc[1] * inv + 0.1 * g_acc[2] * inv
                    + 0.01 * (g_acc[3] / ((double)D_DIM * (double)D_DIM));
        out[out_size - 1] = (float)loss;
    }
}

extern "C" void kernel_launch(void* const* d_in, const int* in_sizes, int n_in,
                              void* d_out, int out_size) {
    const float* x        = (const float*)d_in[0];
    const float* codebook = (const float*)d_in[1];
    const float* rotate   = (const float*)d_in[2];
    float* out = (float*)d_out;

    cudaFuncSetAttribute(pq_kernel, cudaFuncAttributeMaxDynamicSharedMemorySize, PQ_SMEM_BYTES);

    zero_acc_kernel<<<1, 32>>>();
    sgemm_kernel<<<dim3(D_DIM / GBN, N_ROWS / GBM), 256>>>(x, rotate);
    reg_kernel<<<D_DIM, 256>>>(rotate);
    pq_kernel<<<dim3(M_SUB, N_ROWS / ROWS_PB), 512, PQ_SMEM_BYTES>>>(codebook, out);
    finalize_kernel<<<1, 32>>>(out, out_size);
}

// round 16
// speedup vs baseline: 3.5088x; 1.1784x over previous
#include <cuda_runtime.h>
#include <cuda_bf16.h>
#include <math.h>
#include <stdint.h>

#define N_ROWS 131072
#define D_DIM  512
#define M_SUB  4
#define K_CODES 256
#define DM_DIM 128

typedef unsigned long long u64;
typedef unsigned int u32;

// ---- packed fp32x2 helpers (two independent IEEE-754 rn FMAs per instr) ----
__device__ __forceinline__ u64 pack_dup(float a) {
    u64 r; asm("mov.b64 %0, {%1, %1};" : "=l"(r) : "f"(a)); return r;
}
__device__ __forceinline__ void fma2(u64& d, u64 a, u64 b) {
    asm("fma.rn.f32x2 %0, %1, %2, %0;" : "+l"(d) : "l"(a), "l"(b));
}

// ---- tf32 mma.sync helpers (baseline PTX, compiles for plain sm_103) ----
__device__ __forceinline__ u32 f2tf32(float f) {
    u32 u; asm("cvt.rna.tf32.f32 %0, %1;" : "=r"(u) : "f"(f)); return u;
}
__device__ __forceinline__ void mma_tf32(float* c, u32 a0, u32 a1, u32 a2, u32 a3,
                                         u32 b0, u32 b1) {
    asm("mma.sync.aligned.m16n8k8.row.col.f32.tf32.tf32.f32 "
        "{%0,%1,%2,%3},{%4,%5,%6,%7},{%8,%9},{%0,%1,%2,%3};"
        : "+f"(c[0]), "+f"(c[1]), "+f"(c[2]), "+f"(c[3])
        : "r"(a0), "r"(a1), "r"(a2), "r"(a3), "r"(b0), "r"(b1));
}

// scratch: xr = x @ rotate  (268 MB) — static device array (no allocations allowed)
__device__ float g_xr[(size_t)N_ROWS * D_DIM];
__device__ double g_acc[4]; // 0:soft_d sum, 1:hard_d sum, 2:joint sum, 3:reg sum

__global__ void zero_acc_kernel() {
    if (threadIdx.x < 4) g_acc[threadIdx.x] = 0.0;
}

// ---------------------------------------------------------------------------
// Kernel 1: xr = x @ rotate, fp32 FFMA2 SGEMM (unchanged; bit-exact verified).
// ---------------------------------------------------------------------------
#define GBM 128
#define GBN 128
#define GBK 16

__global__ __launch_bounds__(256) void sgemm_kernel(const float* __restrict__ A,
                                                    const float* __restrict__ B) {
    __shared__ float As[GBK][GBM];
    __shared__ float Bs[GBK][GBN];
    const int tid = threadIdx.x;
    const int tx = tid & 15, ty = tid >> 4;
    const int R0 = blockIdx.y * GBM, C0 = blockIdx.x * GBN;

    u64 acc2[8][4];
#pragma unroll
    for (int i = 0; i < 8; i++)
#pragma unroll
        for (int j = 0; j < 4; j++) acc2[i][j] = 0ull;

    for (int k0 = 0; k0 < D_DIM; k0 += GBK) {
#pragma unroll
        for (int t = 0; t < 2; t++) {
            int f = tid + t * 256;
            int row = f >> 2, c4 = f & 3;
            float4 v = *(const float4*)(A + (size_t)(R0 + row) * D_DIM + k0 + c4 * 4);
            As[c4 * 4 + 0][row] = v.x;
            As[c4 * 4 + 1][row] = v.y;
            As[c4 * 4 + 2][row] = v.z;
            As[c4 * 4 + 3][row] = v.w;
        }
#pragma unroll
        for (int t = 0; t < 2; t++) {
            int f = tid + t * 256;
            int row = f >> 5, c4 = f & 31;
            float4 v = *(const float4*)(B + (size_t)(k0 + row) * D_DIM + C0 + c4 * 4);
            *(float4*)(&Bs[row][c4 * 4]) = v;
        }
        __syncthreads();

#pragma unroll
        for (int kk = 0; kk < GBK; kk++) {
            float a[8];
            *(float4*)(a)     = *(const float4*)(&As[kk][ty * 8]);
            *(float4*)(a + 4) = *(const float4*)(&As[kk][ty * 8 + 4]);
            ulonglong2 b01 = *(const ulonglong2*)(&Bs[kk][tx * 8]);
            ulonglong2 b23 = *(const ulonglong2*)(&Bs[kk][tx * 8 + 4]);
            u64 bb0 = b01.x, bb1 = b01.y, bb2 = b23.x, bb3 = b23.y;
#pragma unroll
            for (int i = 0; i < 8; i++) {
                u64 ad = pack_dup(a[i]);
                fma2(acc2[i][0], ad, bb0);
                fma2(acc2[i][1], ad, bb1);
                fma2(acc2[i][2], ad, bb2);
                fma2(acc2[i][3], ad, bb3);
            }
        }
        __syncthreads();
    }
#pragma unroll
    for (int i = 0; i < 8; i++) {
        float* orow = g_xr + (size_t)(R0 + ty * 8 + i) * D_DIM + C0 + tx * 8;
        ulonglong2 v0, v1;
        v0.x = acc2[i][0]; v0.y = acc2[i][1];
        v1.x = acc2[i][2]; v1.y = acc2[i][3];
        *(ulonglong2*)(orow)     = v0;
        *(ulonglong2*)(orow + 4) = v1;
    }
}

// ---------------------------------------------------------------------------
// Kernel 2: reg = sum((R R^T - I)^2)  (loss-only)
// ---------------------------------------------------------------------------
__global__ __launch_bounds__(256) void reg_kernel(const float* __restrict__ R) {
    __shared__ float ri[D_DIM];
    __shared__ float part[8];
    const int i = blockIdx.x;
    const int tid = threadIdx.x;
    for (int d = tid; d < D_DIM; d += 256) ri[d] = R[(size_t)i * D_DIM + d];
    __syncthreads();

    const int warp = tid >> 5, lane = tid & 31;
    float accum = 0.f;
    for (int j = warp; j < D_DIM; j += 8) {
        const float* rj = R + (size_t)j * D_DIM;
        float dot = 0.f;
#pragma unroll 4
        for (int k = lane; k < D_DIM; k += 32) dot += ri[k] * rj[k];
#pragma unroll
        for (int off = 16; off; off >>= 1) dot += __shfl_down_sync(0xffffffffu, dot, off);
        if (lane == 0) {
            float v = dot - (j == i ? 1.f : 0.f);
            accum += v * v;
        }
    }
    if (lane == 0) part[warp] = accum;
    __syncthreads();
    if (tid == 0) {
        float s = 0.f;
#pragma unroll
        for (int w = 0; w < 8; w++) s += part[w];
        atomicAdd(&g_acc[3], (double)s);
    }
}

// ---------------------------------------------------------------------------
// Kernel 3 (v3): mma.sync TF32 SCREEN + exact fp32 candidate recompute.
//
// Screen error <= 2*2^-10*||s||*||c|| (~6) + bf16 store (~4); MARGIN=80 >>
// 35 + 2*10, so the candidate set provably contains the true argmax, all
// exact ties, and every code with exact lsh > -35.
// Exact path per candidate: BIT-EXACT fp32 chain (single accumulator,
// ascending d, IEEE FMA), dist = fl(fl(x2-2xc)+c2) — identical to rounds 5-10.
// Candidates sorted by k => lowest-index ties, deterministic sums.
// ---------------------------------------------------------------------------
#define HROWS 64
#define NHALF 4
#define CAP 16
#define MARGIN 80.0f
#define CPAD 132

#define B_OFF   0
#define A_OFF   (B_OFF + 256 * CPAD * 4)      /* 135168 */
#define SC_OFF  (A_OFF + HROWS * CPAD * 4)    /* 168960 */
#define C2_OFF  (SC_OFF + HROWS * CPAD * 4)   /* 202752 */
#define X2_OFF  (C2_OFF + 1024)
#define CNT_OFF (X2_OFF + 256)
#define CK_OFF  (CNT_OFF + 256)
#define EL_OFF  (CK_OFF + HROWS * CAP * 4)
#define RI_OFF  (EL_OFF + HROWS * CAP * 4)
#define RA_OFF  (RI_OFF + 256)
#define RED_OFF (RA_OFF + 256)
#define PQ2_SMEM (RED_OFF + 3 * 256 * 4)      /* 216064 B */

__global__ __launch_bounds__(256, 1) void pq_kernel(const float* __restrict__ codebook,
                                                    float* __restrict__ out) {
    extern __shared__ char smc[];
    float* cbk  = (float*)(smc + B_OFF);     // [256][132] codebook k-major
    float* Arow = (float*)(smc + A_OFF);     // [64][132] splits (raw fp32)
    u32*   scrU = (u32*)(smc + SC_OFF);      // [64][132] bf16x2 screen t-vals
    float* c2s  = (float*)(smc + C2_OFF);
    float* x2s  = (float*)(smc + X2_OFF);
    int*   cnt  = (int*)(smc + CNT_OFF);
    int*   candk = (int*)(smc + CK_OFF);
    float* exlg = (float*)(smc + EL_OFF);
    float* rinv = (float*)(smc + RI_OFF);
    int*   rarg = (int*)(smc + RA_OFF);
    float* red  = (float*)(smc + RED_OFF);

    const int m   = blockIdx.x;
    const int nb  = blockIdx.y;
    const int tid = threadIdx.x;
    const int lane = tid & 31, warp = tid >> 5;
    const int g = lane >> 2, t = lane & 3;
    const int base = nb * (HROWS * NHALF);

    // ---- stage codebook[m] (raw fp32, pad 132) ----
    const float* cbm = codebook + (size_t)m * K_CODES * DM_DIM;
#pragma unroll
    for (int i = 0; i < 32; i++) {
        int idx = tid + i * 256;
        int k = idx >> 5, d4 = idx & 31;
        *(float4*)(cbk + k * CPAD + d4 * 4) = *(const float4*)(cbm + (size_t)k * DM_DIM + d4 * 4);
    }
    __syncthreads();
    {   // c2[k]: BIT-EXACT sequential ascending, rounded mul then add
        float s = 0.f;
        const float* ck = cbk + tid * CPAD;
        for (int d = 0; d < DM_DIM; d++) {
            float c = ck[d];
            s = __fadd_rn(s, __fmul_rn(c, c));
        }
        c2s[tid] = s;
    }

    float aS = 0.f, aH = 0.f, aJ = 0.f;

    for (int h = 0; h < NHALF; h++) {
        const int rS = base + h * HROWS;
        __syncthreads();   // protect A/scr reuse across halves

        // ---- stage A half (64 rows, raw fp32) ----
#pragma unroll
        for (int i = 0; i < 8; i++) {
            int idx = tid + i * 256;
            int row = idx >> 5, d4 = idx & 31;
            *(float4*)(Arow + row * CPAD + d4 * 4) =
                *(const float4*)(g_xr + (size_t)(rS + row) * D_DIM + m * DM_DIM + d4 * 4);
        }
        if (tid < HROWS) cnt[tid] = 0;
        __syncthreads();

        if (tid < HROWS) {  // x2: BIT-EXACT sequential ascending d
            float s = 0.f;
            const float* ar = Arow + tid * CPAD;
            for (int d = 0; d < DM_DIM; d++) {
                float v = ar[d];
                s = __fadd_rn(s, __fmul_rn(v, v));
            }
            x2s[tid] = s;
        }

        // ---- TF32 screen: warp = 16 rows x 128 codes (16 n-tiles) ----
        {
            const int rowb = (warp & 3) * 16;
            const int cb   = (warp >> 2) * 128;
            float acc[16][4];
#pragma unroll
            for (int nt = 0; nt < 16; nt++)
#pragma unroll
                for (int j = 0; j < 4; j++) acc[nt][j] = 0.f;

#pragma unroll 2
            for (int kt = 0; kt < 16; kt++) {
                int k0 = kt * 8;
                u32 a0 = f2tf32(Arow[(rowb + g) * CPAD + k0 + t]);
                u32 a1 = f2tf32(Arow[(rowb + g + 8) * CPAD + k0 + t]);
                u32 a2 = f2tf32(Arow[(rowb + g) * CPAD + k0 + t + 4]);
                u32 a3 = f2tf32(Arow[(rowb + g + 8) * CPAD + k0 + t + 4]);
#pragma unroll
                for (int nt = 0; nt < 16; nt++) {
                    int n0 = cb + nt * 8;
                    u32 b0 = f2tf32(cbk[(n0 + g) * CPAD + k0 + t]);
                    u32 b1 = f2tf32(cbk[(n0 + g) * CPAD + k0 + t + 4]);
                    mma_tf32(acc[nt], a0, a1, a2, a3, b0, b1);
                }
            }
            // t = 2*D - c2, store bf16-packed (cols 2t,2t+1 adjacent)
#pragma unroll
            for (int nt = 0; nt < 16; nt++) {
                int n0 = cb + nt * 8;
                int colU = (cb >> 1) + nt * 4 + t;
                float c2a = c2s[n0 + 2 * t], c2b = c2s[n0 + 2 * t + 1];
                __nv_bfloat162 lo = __floats2bfloat162_rn(2.f * acc[nt][0] - c2a,
                                                          2.f * acc[nt][1] - c2b);
                __nv_bfloat162 hi = __floats2bfloat162_rn(2.f * acc[nt][2] - c2a,
                                                          2.f * acc[nt][3] - c2b);
                scrU[(rowb + g) * CPAD + colU]     = *(u32*)&lo;
                scrU[(rowb + g + 8) * CPAD + colU] = *(u32*)&hi;
            }
        }
        __syncthreads();

        // ---- scan: row max (4 threads/row) + candidate emit ----
        {
            int r = tid >> 2, q = tid & 3;
            const u32* sr = scrU + r * CPAD + q * 32;
            float mx = -3.4e38f;
#pragma unroll 8
            for (int i = 0; i < 32; i++) {
                float2 f = __bfloat1622float2(*(const __nv_bfloat162*)(sr + i));
                mx = fmaxf(mx, fmaxf(f.x, f.y));
            }
            mx = fmaxf(mx, __shfl_xor_sync(0xffffffffu, mx, 1));
            mx = fmaxf(mx, __shfl_xor_sync(0xffffffffu, mx, 2));
            float thr = mx - MARGIN;
#pragma unroll 8
            for (int i = 0; i < 32; i++) {
                float2 f = __bfloat1622float2(*(const __nv_bfloat162*)(sr + i));
                if (f.x > thr) {
                    int s = atomicAdd(&cnt[r], 1);
                    if (s < CAP) candk[r * CAP + s] = q * 64 + 2 * i;
                }
                if (f.y > thr) {
                    int s = atomicAdd(&cnt[r], 1);
                    if (s < CAP) candk[r * CAP + s] = q * 64 + 2 * i + 1;
                }
            }
        }
        __syncthreads();

        // ---- exact recompute: BIT-EXACT fp32 chain per candidate ----
        {
            int r = tid & 63, which = tid >> 6;
            int n = min(cnt[r], CAP);
            for (int j = which; j < n; j += 4) {
                int k = candk[r * CAP + j];
                const float* ar = Arow + r * CPAD;
                const float* ck = cbk + k * CPAD;
                float acc = 0.f;
                for (int d = 0; d < DM_DIM; d++)
                    acc = __fmaf_rn(ar[d], ck[d], acc);
                exlg[r * CAP + j] = -__fadd_rn(__fadd_rn(x2s[r], -(2.0f * acc)), c2s[k]);
            }
        }
        __syncthreads();

        // ---- finalize per row: sort by k, argmax (lowest-k ties), Z ----
        if (tid < HROWS) {
            int r = tid;
            int n = min(cnt[r], CAP);
            int kk[CAP]; float lv[CAP];
            for (int j = 0; j < n; j++) { kk[j] = candk[r * CAP + j]; lv[j] = exlg[r * CAP + j]; }
            for (int i = 0; i < n - 1; i++) {
                int mn = i;
                for (int j = i + 1; j < n; j++) if (kk[j] < kk[mn]) mn = j;
                int tk = kk[i]; kk[i] = kk[mn]; kk[mn] = tk;
                float tl = lv[i]; lv[i] = lv[mn]; lv[mn] = tl;
            }
            float best = lv[0]; int bk = kk[0];
            for (int j = 1; j < n; j++) if (lv[j] > best) { best = lv[j]; bk = kk[j]; }
            float Z = 0.f;
            for (int j = 0; j < n; j++) {
                float e = __expf(lv[j] - best);
                exlg[r * CAP + j] = e;
                candk[r * CAP + j] = kk[j];
                Z += e;
            }
            rarg[r] = bk;
            rinv[r] = 1.f / Z;
            out[(size_t)(rS + r) * M_SUB + m] = (float)bk;   // hard code
        }
        __syncthreads();

        // ---- sparse soft recon + losses: warp -> 8 rows, lane -> 4 dims ----
        {
            const int d0 = lane * 4;
#pragma unroll
            for (int rr = 0; rr < 8; rr++) {
                int r = warp * 8 + rr;
                int n = min(cnt[r], CAP);
                float sx = 0.f, sy = 0.f, sz = 0.f, sw = 0.f;
                for (int s = 0; s < n; s++) {
                    int k = candk[r * CAP + s];
                    float e = exlg[r * CAP + s];
                    float4 cv = *(const float4*)(cbk + k * CPAD + d0);
                    sx += e * cv.x; sy += e * cv.y; sz += e * cv.z; sw += e * cv.w;
                }
                float inv = rinv[r];
                float4 sp = *(const float4*)(Arow + r * CPAD + d0);
                float4 hd = *(const float4*)(cbk + rarg[r] * CPAD + d0);
                float soft[4] = { sx * inv, sy * inv, sz * inv, sw * inv };
                float spv[4] = { sp.x, sp.y, sp.z, sp.w };
                float hdv[4] = { hd.x, hd.y, hd.z, hd.w };
#pragma unroll
                for (int tt = 0; tt < 4; tt++) {
                    float ds = spv[tt] - soft[tt];
                    float dh = spv[tt] - hdv[tt];
                    float dj = soft[tt] - hdv[tt];
                    aS += ds * ds;
                    aH += dh * dh;
                    aJ += dj * dj;
                }
            }
        }
    }
    __syncthreads();

    // ---- block-reduce the 3 loss partials ----
    red[tid] = aS; red[256 + tid] = aH; red[512 + tid] = aJ;
    __syncthreads();
    for (int s = 128; s > 0; s >>= 1) {
        if (tid < s) {
            red[tid]       += red[tid + s];
            red[256 + tid] += red[256 + tid + s];
            red[512 + tid] += red[512 + tid + s];
        }
        __syncthreads();
    }
    if (tid == 0) {
        atomicAdd(&g_acc[0], (double)red[0]);
        atomicAdd(&g_acc[1], (double)red[256]);
        atomicAdd(&g_acc[2], (double)red[512]);
    }
}

// ---------------------------------------------------------------------------
// Kernel 4: combine loss
// ---------------------------------------------------------------------------
__global__ void finalize_kernel(float* out, int out_size) {
    if (threadIdx.x == 0) {
        double inv = 1.0 / ((double)N_ROWS * (double)DM_DIM);
        double loss = 0.1 * g_acc[0] * inv + g_acc[1] * inv + 0.1 * g_acc[2] * inv
                    + 0.01 * (g_acc[3] / ((double)D_DIM * (double)D_DIM));
        out[out_size - 1] = (float)loss;
    }
}

extern "C" void kernel_launch(void* const* d_in, const int* in_sizes, int n_in,
                              void* d_out, int out_size) {
    const float* x        = (const float*)d_in[0];
    const float* codebook = (const float*)d_in[1];
    const float* rotate   = (const float*)d_in[2];
    float* out = (float*)d_out;

    cudaFuncSetAttribute(pq_kernel, cudaFuncAttributeMaxDynamicSharedMemorySize, PQ2_SMEM);

    zero_acc_kernel<<<1, 32>>>();
    sgemm_kernel<<<dim3(D_DIM / GBN, N_ROWS / GBM), 256>>>(x, rotate);
    reg_kernel<<<D_DIM, 256>>>(rotate);
    pq_kernel<<<dim3(M_SUB, N_ROWS / (HROWS * NHALF)), 256, PQ2_SMEM>>>(codebook, out);
    finalize_kernel<<<1, 32>>>(out, out_size);
}

// round 17
// speedup vs baseline: 3.6715x; 1.0464x over previous
#include <cuda_runtime.h>
#include <cuda_bf16.h>
#include <math.h>
#include <stdint.h>

#define N_ROWS 131072
#define D_DIM  512
#define M_SUB  4
#define K_CODES 256
#define DM_DIM 128

typedef unsigned long long u64;
typedef unsigned int u32;

// ---- packed fp32x2 helpers (two independent IEEE-754 rn FMAs per instr) ----
__device__ __forceinline__ u64 pack_dup(float a) {
    u64 r; asm("mov.b64 %0, {%1, %1};" : "=l"(r) : "f"(a)); return r;
}
__device__ __forceinline__ void fma2(u64& d, u64 a, u64 b) {
    asm("fma.rn.f32x2 %0, %1, %2, %0;" : "+l"(d) : "l"(a), "l"(b));
}

// ---- tf32 mma.sync helpers (baseline PTX, compiles for plain sm_103) ----
__device__ __forceinline__ u32 f2tf32(float f) {
    u32 u; asm("cvt.rna.tf32.f32 %0, %1;" : "=r"(u) : "f"(f)); return u;
}
__device__ __forceinline__ void mma_tf32(float* c, u32 a0, u32 a1, u32 a2, u32 a3,
                                         u32 b0, u32 b1) {
    asm("mma.sync.aligned.m16n8k8.row.col.f32.tf32.tf32.f32 "
        "{%0,%1,%2,%3},{%4,%5,%6,%7},{%8,%9},{%0,%1,%2,%3};"
        : "+f"(c[0]), "+f"(c[1]), "+f"(c[2]), "+f"(c[3])
        : "r"(a0), "r"(a1), "r"(a2), "r"(a3), "r"(b0), "r"(b1));
}

// scratch: xr = x @ rotate  (268 MB) — static device array (no allocations allowed)
__device__ float g_xr[(size_t)N_ROWS * D_DIM];
__device__ double g_acc[4]; // 0:soft_d sum, 1:hard_d sum, 2:joint sum, 3:reg sum

__global__ void zero_acc_kernel() {
    if (threadIdx.x < 4) g_acc[threadIdx.x] = 0.0;
}

// ---------------------------------------------------------------------------
// Kernel 1: xr = x @ rotate, fp32 FFMA2 SGEMM, double-buffered smem.
// BIT-EXACT: single accumulator, strictly ascending k, IEEE rn FMA —
// arithmetic identical to rounds 8-16 (verified rel_err==0).
// ---------------------------------------------------------------------------
#define GBM 128
#define GBN 128
#define GBK 16
#define GNK (D_DIM / GBK)   /* 32 */

__global__ __launch_bounds__(256, 2) void sgemm_kernel(const float* __restrict__ A,
                                                       const float* __restrict__ B) {
    __shared__ float As[2][GBK][GBM];
    __shared__ float Bs[2][GBK][GBN];
    const int tid = threadIdx.x;
    const int tx = tid & 15, ty = tid >> 4;
    const int R0 = blockIdx.y * GBM, C0 = blockIdx.x * GBN;

    // per-thread load coords (fixed across stages)
    const int arow0 = tid >> 2,          ac0 = tid & 3;
    const int arow1 = (tid + 256) >> 2,  ac1 = (tid + 256) & 3;
    const int brow0 = tid >> 5,          bc0 = tid & 31;
    const int brow1 = (tid + 256) >> 5,  bc1 = (tid + 256) & 31;

    u64 acc2[8][4];
#pragma unroll
    for (int i = 0; i < 8; i++)
#pragma unroll
        for (int j = 0; j < 4; j++) acc2[i][j] = 0ull;

    // prologue: stage 0
    {
        float4 v;
        v = *(const float4*)(A + (size_t)(R0 + arow0) * D_DIM + ac0 * 4);
        As[0][ac0 * 4 + 0][arow0] = v.x; As[0][ac0 * 4 + 1][arow0] = v.y;
        As[0][ac0 * 4 + 2][arow0] = v.z; As[0][ac0 * 4 + 3][arow0] = v.w;
        v = *(const float4*)(A + (size_t)(R0 + arow1) * D_DIM + ac1 * 4);
        As[0][ac1 * 4 + 0][arow1] = v.x; As[0][ac1 * 4 + 1][arow1] = v.y;
        As[0][ac1 * 4 + 2][arow1] = v.z; As[0][ac1 * 4 + 3][arow1] = v.w;
        *(float4*)(&Bs[0][brow0][bc0 * 4]) = *(const float4*)(B + (size_t)brow0 * D_DIM + C0 + bc0 * 4);
        *(float4*)(&Bs[0][brow1][bc1 * 4]) = *(const float4*)(B + (size_t)brow1 * D_DIM + C0 + bc1 * 4);
    }
    __syncthreads();

    for (int kt = 0; kt < GNK; kt++) {
        const int cur = kt & 1;
        float4 pa0, pa1, pb0, pb1;
        if (kt + 1 < GNK) {
            int k0 = (kt + 1) * GBK;
            pa0 = *(const float4*)(A + (size_t)(R0 + arow0) * D_DIM + k0 + ac0 * 4);
            pa1 = *(const float4*)(A + (size_t)(R0 + arow1) * D_DIM + k0 + ac1 * 4);
            pb0 = *(const float4*)(B + (size_t)(k0 + brow0) * D_DIM + C0 + bc0 * 4);
            pb1 = *(const float4*)(B + (size_t)(k0 + brow1) * D_DIM + C0 + bc1 * 4);
        }
#pragma unroll
        for (int kk = 0; kk < GBK; kk++) {
            float a[8];
            *(float4*)(a)     = *(const float4*)(&As[cur][kk][ty * 8]);
            *(float4*)(a + 4) = *(const float4*)(&As[cur][kk][ty * 8 + 4]);
            ulonglong2 b01 = *(const ulonglong2*)(&Bs[cur][kk][tx * 8]);
            ulonglong2 b23 = *(const ulonglong2*)(&Bs[cur][kk][tx * 8 + 4]);
            u64 bb0 = b01.x, bb1 = b01.y, bb2 = b23.x, bb3 = b23.y;
#pragma unroll
            for (int i = 0; i < 8; i++) {
                u64 ad = pack_dup(a[i]);
                fma2(acc2[i][0], ad, bb0);
                fma2(acc2[i][1], ad, bb1);
                fma2(acc2[i][2], ad, bb2);
                fma2(acc2[i][3], ad, bb3);
            }
        }
        if (kt + 1 < GNK) {
            const int nxt = cur ^ 1;
            As[nxt][ac0 * 4 + 0][arow0] = pa0.x; As[nxt][ac0 * 4 + 1][arow0] = pa0.y;
            As[nxt][ac0 * 4 + 2][arow0] = pa0.z; As[nxt][ac0 * 4 + 3][arow0] = pa0.w;
            As[nxt][ac1 * 4 + 0][arow1] = pa1.x; As[nxt][ac1 * 4 + 1][arow1] = pa1.y;
            As[nxt][ac1 * 4 + 2][arow1] = pa1.z; As[nxt][ac1 * 4 + 3][arow1] = pa1.w;
            *(float4*)(&Bs[nxt][brow0][bc0 * 4]) = pb0;
            *(float4*)(&Bs[nxt][brow1][bc1 * 4]) = pb1;
        }
        __syncthreads();
    }
#pragma unroll
    for (int i = 0; i < 8; i++) {
        float* orow = g_xr + (size_t)(R0 + ty * 8 + i) * D_DIM + C0 + tx * 8;
        ulonglong2 v0, v1;
        v0.x = acc2[i][0]; v0.y = acc2[i][1];
        v1.x = acc2[i][2]; v1.y = acc2[i][3];
        *(ulonglong2*)(orow)     = v0;
        *(ulonglong2*)(orow + 4) = v1;
    }
}

// ---------------------------------------------------------------------------
// Kernel 2: reg = sum((R R^T - I)^2)  (loss-only)
// ---------------------------------------------------------------------------
__global__ __launch_bounds__(256) void reg_kernel(const float* __restrict__ R) {
    __shared__ float ri[D_DIM];
    __shared__ float part[8];
    const int i = blockIdx.x;
    const int tid = threadIdx.x;
    for (int d = tid; d < D_DIM; d += 256) ri[d] = R[(size_t)i * D_DIM + d];
    __syncthreads();

    const int warp = tid >> 5, lane = tid & 31;
    float accum = 0.f;
    for (int j = warp; j < D_DIM; j += 8) {
        const float* rj = R + (size_t)j * D_DIM;
        float dot = 0.f;
#pragma unroll 4
        for (int k = lane; k < D_DIM; k += 32) dot += ri[k] * rj[k];
#pragma unroll
        for (int off = 16; off; off >>= 1) dot += __shfl_down_sync(0xffffffffu, dot, off);
        if (lane == 0) {
            float v = dot - (j == i ? 1.f : 0.f);
            accum += v * v;
        }
    }
    if (lane == 0) part[warp] = accum;
    __syncthreads();
    if (tid == 0) {
        float s = 0.f;
#pragma unroll
        for (int w = 0; w < 8; w++) s += part[w];
        atomicAdd(&g_acc[3], (double)s);
    }
}

// ---------------------------------------------------------------------------
// Kernel 3 (v4): mma.sync TF32 SCREEN + exact fp32 candidate recompute.
// 512 threads (16 warps). Screen/exact arithmetic identical to round 16
// (verified rel_err==0); only the thread mapping changed.
// ---------------------------------------------------------------------------
#define HROWS 64
#define NHALF 4
#define CAP 16
#define MARGIN 80.0f
#define CPAD 132

#define B_OFF   0
#define A_OFF   (B_OFF + 256 * CPAD * 4)      /* 135168 */
#define SC_OFF  (A_OFF + HROWS * CPAD * 4)    /* 168960 */
#define C2_OFF  (SC_OFF + HROWS * CPAD * 4)   /* 202752 */
#define X2_OFF  (C2_OFF + 1024)
#define CNT_OFF (X2_OFF + 256)
#define CK_OFF  (CNT_OFF + 256)
#define EL_OFF  (CK_OFF + HROWS * CAP * 4)
#define RI_OFF  (EL_OFF + HROWS * CAP * 4)
#define RA_OFF  (RI_OFF + 256)
#define RED_OFF (RA_OFF + 256)
#define PQ2_SMEM (RED_OFF + 3 * 512 * 4)      /* 219136 B */

__global__ __launch_bounds__(512, 1) void pq_kernel(const float* __restrict__ codebook,
                                                    float* __restrict__ out) {
    extern __shared__ char smc[];
    float* cbk  = (float*)(smc + B_OFF);     // [256][132] codebook k-major (raw fp32)
    float* Arow = (float*)(smc + A_OFF);     // [64][132] splits (raw fp32)
    u32*   scrU = (u32*)(smc + SC_OFF);      // [64][132] bf16x2 screen t-vals
    float* c2s  = (float*)(smc + C2_OFF);
    float* x2s  = (float*)(smc + X2_OFF);
    int*   cnt  = (int*)(smc + CNT_OFF);
    int*   candk = (int*)(smc + CK_OFF);
    float* exlg = (float*)(smc + EL_OFF);
    float* rinv = (float*)(smc + RI_OFF);
    int*   rarg = (int*)(smc + RA_OFF);
    float* red  = (float*)(smc + RED_OFF);

    const int m   = blockIdx.x;
    const int nb  = blockIdx.y;
    const int tid = threadIdx.x;
    const int lane = tid & 31, warp = tid >> 5;
    const int g = lane >> 2, t = lane & 3;
    const int base = nb * (HROWS * NHALF);

    // ---- stage codebook[m] (raw fp32, pad 132) ----
    const float* cbm = codebook + (size_t)m * K_CODES * DM_DIM;
#pragma unroll
    for (int i = 0; i < 16; i++) {
        int idx = tid + i * 512;
        int k = idx >> 5, d4 = idx & 31;
        *(float4*)(cbk + k * CPAD + d4 * 4) = *(const float4*)(cbm + (size_t)k * DM_DIM + d4 * 4);
    }
    __syncthreads();
    if (tid < 256) {   // c2[k]: BIT-EXACT sequential ascending, rounded mul then add
        float s = 0.f;
        const float* ck = cbk + tid * CPAD;
        for (int d = 0; d < DM_DIM; d++) {
            float c = ck[d];
            s = __fadd_rn(s, __fmul_rn(c, c));
        }
        c2s[tid] = s;
    }

    float aS = 0.f, aH = 0.f, aJ = 0.f;

    for (int h = 0; h < NHALF; h++) {
        const int rS = base + h * HROWS;
        __syncthreads();   // protect A/scr reuse across halves

        // ---- stage A half (64 rows, raw fp32) ----
#pragma unroll
        for (int i = 0; i < 4; i++) {
            int idx = tid + i * 512;
            int row = idx >> 5, d4 = idx & 31;
            *(float4*)(Arow + row * CPAD + d4 * 4) =
                *(const float4*)(g_xr + (size_t)(rS + row) * D_DIM + m * DM_DIM + d4 * 4);
        }
        if (tid < HROWS) cnt[tid] = 0;
        __syncthreads();

        if (tid < HROWS) {  // x2: BIT-EXACT sequential ascending d
            float s = 0.f;
            const float* ar = Arow + tid * CPAD;
            for (int d = 0; d < DM_DIM; d++) {
                float v = ar[d];
                s = __fadd_rn(s, __fmul_rn(v, v));
            }
            x2s[tid] = s;
        }

        // ---- TF32 screen: warp = 16 rows x 64 codes (8 n-tiles) ----
        {
            const int rowb = (warp & 3) * 16;
            const int cb   = (warp >> 2) * 64;
            float acc[8][4];
#pragma unroll
            for (int nt = 0; nt < 8; nt++)
#pragma unroll
                for (int j = 0; j < 4; j++) acc[nt][j] = 0.f;

#pragma unroll 4
            for (int kt = 0; kt < 16; kt++) {
                int k0 = kt * 8;
                u32 a0 = f2tf32(Arow[(rowb + g) * CPAD + k0 + t]);
                u32 a1 = f2tf32(Arow[(rowb + g + 8) * CPAD + k0 + t]);
                u32 a2 = f2tf32(Arow[(rowb + g) * CPAD + k0 + t + 4]);
                u32 a3 = f2tf32(Arow[(rowb + g + 8) * CPAD + k0 + t + 4]);
#pragma unroll
                for (int nt = 0; nt < 8; nt++) {
                    int n0 = cb + nt * 8;
                    u32 b0 = f2tf32(cbk[(n0 + g) * CPAD + k0 + t]);
                    u32 b1 = f2tf32(cbk[(n0 + g) * CPAD + k0 + t + 4]);
                    mma_tf32(acc[nt], a0, a1, a2, a3, b0, b1);
                }
            }
            // t = 2*D - c2, store bf16-packed (codes 2t, 2t+1 per u32)
#pragma unroll
            for (int nt = 0; nt < 8; nt++) {
                int n0 = cb + nt * 8;
                int colU = (cb >> 1) + nt * 4 + t;
                float c2a = c2s[n0 + 2 * t], c2b = c2s[n0 + 2 * t + 1];
                __nv_bfloat162 lo = __floats2bfloat162_rn(2.f * acc[nt][0] - c2a,
                                                          2.f * acc[nt][1] - c2b);
                __nv_bfloat162 hi = __floats2bfloat162_rn(2.f * acc[nt][2] - c2a,
                                                          2.f * acc[nt][3] - c2b);
                scrU[(rowb + g) * CPAD + colU]     = *(u32*)&lo;
                scrU[(rowb + g + 8) * CPAD + colU] = *(u32*)&hi;
            }
        }
        __syncthreads();

        // ---- scan: row max (8 threads/row) + candidate emit ----
        {
            int r = tid >> 3, q = tid & 7;
            const u32* sr = scrU + r * CPAD + q * 16;
            float mx = -3.4e38f;
#pragma unroll 8
            for (int i = 0; i < 16; i++) {
                float2 f = __bfloat1622float2(*(const __nv_bfloat162*)(sr + i));
                mx = fmaxf(mx, fmaxf(f.x, f.y));
            }
            mx = fmaxf(mx, __shfl_xor_sync(0xffffffffu, mx, 1));
            mx = fmaxf(mx, __shfl_xor_sync(0xffffffffu, mx, 2));
            mx = fmaxf(mx, __shfl_xor_sync(0xffffffffu, mx, 4));
            float thr = mx - MARGIN;
#pragma unroll 8
            for (int i = 0; i < 16; i++) {
                float2 f = __bfloat1622float2(*(const __nv_bfloat162*)(sr + i));
                if (f.x > thr) {
                    int s = atomicAdd(&cnt[r], 1);
                    if (s < CAP) candk[r * CAP + s] = q * 32 + 2 * i;
                }
                if (f.y > thr) {
                    int s = atomicAdd(&cnt[r], 1);
                    if (s < CAP) candk[r * CAP + s] = q * 32 + 2 * i + 1;
                }
            }
        }
        __syncthreads();

        // ---- exact recompute: BIT-EXACT fp32 chain per candidate ----
        {
            int r = tid & 63, which = tid >> 6;
            int n = min(cnt[r], CAP);
            for (int j = which; j < n; j += 8) {
                int k = candk[r * CAP + j];
                const float* ar = Arow + r * CPAD;
                const float* ck = cbk + k * CPAD;
                float acc = 0.f;
                for (int d = 0; d < DM_DIM; d++)
                    acc = __fmaf_rn(ar[d], ck[d], acc);
                exlg[r * CAP + j] = -__fadd_rn(__fadd_rn(x2s[r], -(2.0f * acc)), c2s[k]);
            }
        }
        __syncthreads();

        // ---- finalize per row: sort by k, argmax (lowest-k ties), Z ----
        if (tid < HROWS) {
            int r = tid;
            int n = min(cnt[r], CAP);
            int kk[CAP]; float lv[CAP];
            for (int j = 0; j < n; j++) { kk[j] = candk[r * CAP + j]; lv[j] = exlg[r * CAP + j]; }
            for (int i = 0; i < n - 1; i++) {
                int mn = i;
                for (int j = i + 1; j < n; j++) if (kk[j] < kk[mn]) mn = j;
                int tk = kk[i]; kk[i] = kk[mn]; kk[mn] = tk;
                float tl = lv[i]; lv[i] = lv[mn]; lv[mn] = tl;
            }
            float best = lv[0]; int bk = kk[0];
            for (int j = 1; j < n; j++) if (lv[j] > best) { best = lv[j]; bk = kk[j]; }
            float Z = 0.f;
            for (int j = 0; j < n; j++) {
                float e = __expf(lv[j] - best);
                exlg[r * CAP + j] = e;
                candk[r * CAP + j] = kk[j];
                Z += e;
            }
            rarg[r] = bk;
            rinv[r] = 1.f / Z;
            out[(size_t)(rS + r) * M_SUB + m] = (float)bk;   // hard code
        }
        __syncthreads();

        // ---- sparse soft recon + losses: warp -> 4 rows, lane -> 4 dims ----
        {
            const int d0 = lane * 4;
#pragma unroll
            for (int rr = 0; rr < 4; rr++) {
                int r = warp * 4 + rr;
                int n = min(cnt[r], CAP);
                float sx = 0.f, sy = 0.f, sz = 0.f, sw = 0.f;
                for (int s = 0; s < n; s++) {
                    int k = candk[r * CAP + s];
                    float e = exlg[r * CAP + s];
                    float4 cv = *(const float4*)(cbk + k * CPAD + d0);
                    sx += e * cv.x; sy += e * cv.y; sz += e * cv.z; sw += e * cv.w;
                }
                float inv = rinv[r];
                float4 sp = *(const float4*)(Arow + r * CPAD + d0);
                float4 hd = *(const float4*)(cbk + rarg[r] * CPAD + d0);
                float soft[4] = { sx * inv, sy * inv, sz * inv, sw * inv };
                float spv[4] = { sp.x, sp.y, sp.z, sp.w };
                float hdv[4] = { hd.x, hd.y, hd.z, hd.w };
#pragma unroll
                for (int tt = 0; tt < 4; tt++) {
                    float ds = spv[tt] - soft[tt];
                    float dh = spv[tt] - hdv[tt];
                    float dj = soft[tt] - hdv[tt];
                    aS += ds * ds;
                    aH += dh * dh;
                    aJ += dj * dj;
                }
            }
        }
    }
    __syncthreads();

    // ---- block-reduce the 3 loss partials ----
    red[tid] = aS; red[512 + tid] = aH; red[1024 + tid] = aJ;
    __syncthreads();
    for (int s = 256; s > 0; s >>= 1) {
        if (tid < s) {
            red[tid]        += red[tid + s];
            red[512 + tid]  += red[512 + tid + s];
            red[1024 + tid] += red[1024 + tid + s];
        }
        __syncthreads();
    }
    if (tid == 0) {
        atomicAdd(&g_acc[0], (double)red[0]);
        atomicAdd(&g_acc[1], (double)red[512]);
        atomicAdd(&g_acc[2], (double)red[1024]);
    }
}

// ---------------------------------------------------------------------------
// Kernel 4: combine loss
// ---------------------------------------------------------------------------
__global__ void finalize_kernel(float* out, int out_size) {
    if (threadIdx.x == 0) {
        double inv = 1.0 / ((double)N_ROWS * (double)DM_DIM);
        double loss = 0.1 * g_acc[0] * inv + g_acc[1] * inv + 0.1 * g_acc[2] * inv
                    + 0.01 * (g_acc[3] / ((double)D_DIM * (double)D_DIM));
        out[out_size - 1] = (float)loss;
    }
}

extern "C" void kernel_launch(void* const* d_in, const int* in_sizes, int n_in,
                              void* d_out, int out_size) {
    const float* x        = (const float*)d_in[0];
    const float* codebook = (const float*)d_in[1];
    const float* rotate   = (const float*)d_in[2];
    float* out = (float*)d_out;

    cudaFuncSetAttribute(pq_kernel, cudaFuncAttributeMaxDynamicSharedMemorySize, PQ2_SMEM);

    zero_acc_kernel<<<1, 32>>>();
    sgemm_kernel<<<dim3(D_DIM / GBN, N_ROWS / GBM), 256>>>(x, rotate);
    reg_kernel<<<D_DIM, 256>>>(rotate);
    pq_kernel<<<dim3(M_SUB, N_ROWS / (HROWS * NHALF)), 512, PQ2_SMEM>>>(codebook, out);
    finalize_kernel<<<1, 32>>>(out, out_size);
}